// round 2
// baseline (speedup 1.0000x reference)
#include <cuda_runtime.h>
#include <math.h>

#define B_  2
#define S_  2048
#define D_  1024
#define H_  16
#define DH  64
#define M_  (B_*S_)
#define SCALE 0.03125f   // 1024^-0.5

// Scratch (allocation-free rule: __device__ globals)
__device__ float g_Q[M_*D_];
__device__ float g_K[M_*D_];
__device__ float g_V[M_*D_];
__device__ float g_A[M_*D_];

// ---------------------------------------------------------------------------
// GEMM: C[M,N] = A[M,K] @ W[K,N] + bias[N]   (all row-major fp32)
// 64x64 block tile, BK=16, 256 threads, 4x4 register blocking.
// ---------------------------------------------------------------------------
__global__ __launch_bounds__(256) void gemm_bias_kernel(
    const float* __restrict__ A, const float* __restrict__ W,
    const float* __restrict__ bias, float* __restrict__ C,
    int M, int N, int K)
{
    __shared__ float As[16][65];   // [k][m], pad 65 kills 16-way store conflict
    __shared__ float Bs[16][64];   // [k][n]

    const int t  = threadIdx.x;
    const int tx = t & 15;         // n-group
    const int ty = t >> 4;         // m-group
    const int row0 = blockIdx.y * 64;
    const int col0 = blockIdx.x * 64;

    float acc[4][4] = {};

    for (int k0 = 0; k0 < K; k0 += 16) {
        #pragma unroll
        for (int i = 0; i < 4; i++) {
            int idx = t + i * 256;          // 1024 elems of A tile
            int m  = idx >> 4;
            int kk = idx & 15;
            As[kk][m] = A[(size_t)(row0 + m) * K + (k0 + kk)];
        }
        #pragma unroll
        for (int i = 0; i < 4; i++) {
            int idx = t + i * 256;          // 1024 elems of B tile
            int kk = idx >> 6;
            int n  = idx & 63;
            Bs[kk][n] = W[(size_t)(k0 + kk) * N + (col0 + n)];
        }
        __syncthreads();

        #pragma unroll
        for (int kk = 0; kk < 16; kk++) {
            float a[4], b[4];
            #pragma unroll
            for (int i = 0; i < 4; i++) a[i] = As[kk][ty * 4 + i];
            #pragma unroll
            for (int j = 0; j < 4; j++) b[j] = Bs[kk][tx * 4 + j];
            #pragma unroll
            for (int i = 0; i < 4; i++)
                #pragma unroll
                for (int j = 0; j < 4; j++)
                    acc[i][j] = fmaf(a[i], b[j], acc[i][j]);
        }
        __syncthreads();
    }

    #pragma unroll
    for (int i = 0; i < 4; i++) {
        int r = row0 + ty * 4 + i;
        #pragma unroll
        for (int j = 0; j < 4; j++) {
            int c = col0 + tx * 4 + j;
            C[(size_t)r * N + c] = acc[i][j] + bias[c];
        }
    }
}

// ---------------------------------------------------------------------------
// Flash-attention (causal), fp32. One CTA per (b, h, 64-query tile).
// 128 threads. Per 64-key tile:
//   phase 1: S = Q K^T (4x8 register-blocked outer product) -> smem (masked)
//   phase 2: per-query online softmax; 2 threads/query, each owns d/2 = 32
//            output accumulators in registers.
// ---------------------------------------------------------------------------
#define QTILE 64
#define KTILE 64
#define PAD   68   // padded row stride (floats): 4-aligned for float4, conflict-light

// smem layout (floats):
//   QsT [DH][PAD]   (Q transposed, pre-scaled)
//   KsT [DH][PAD]   (K transposed)
//   Vs  [KTILE][DH]
//   Ss  [QTILE][PAD]
#define SMEM_FLOATS (DH*PAD + DH*PAD + KTILE*DH + QTILE*PAD)

__global__ __launch_bounds__(128) void attn_kernel(
    const float* __restrict__ Q, const float* __restrict__ K,
    const float* __restrict__ V, float* __restrict__ O)
{
    extern __shared__ float smem[];
    float* QsT = smem;                 // [DH][PAD]
    float* KsT = QsT + DH * PAD;       // [DH][PAD]
    float* Vs  = KsT + DH * PAD;       // [KTILE][DH]
    float* Ss  = Vs  + KTILE * DH;     // [QTILE][PAD]

    const int t  = threadIdx.x;
    const int qt = blockIdx.x;         // query tile 0..31
    const int h  = blockIdx.y;
    const int b  = blockIdx.z;

    const size_t base = (size_t)b * S_ * D_ + (size_t)h * DH;  // + s*D_ + dd
    const int q0 = qt * QTILE;

    // Load Q tile, transposed + pre-scaled
    for (int idx = t; idx < QTILE * DH; idx += 128) {
        int q  = idx >> 6;
        int dd = idx & 63;
        QsT[dd * PAD + q] = Q[base + (size_t)(q0 + q) * D_ + dd] * SCALE;
    }

    // phase-1 mapping: 16 q-groups x 8 j-groups
    const int qg = t >> 3;   // queries qg*4 .. +3
    const int jg = t & 7;    // keys    jg*8 .. +7
    // phase-2 mapping: 2 threads per query
    const int qi   = t >> 1;
    const int half = t & 1;

    float m = -1e30f, l = 0.f;
    float o[32];
    #pragma unroll
    for (int i = 0; i < 32; i++) o[i] = 0.f;

    __syncthreads();

    for (int kt = 0; kt <= qt; kt++) {
        const int k0 = kt * KTILE;

        // Load K (transposed) and V (direct) tiles
        for (int idx = t; idx < KTILE * DH; idx += 128) {
            int j  = idx >> 6;
            int dd = idx & 63;
            size_t g = base + (size_t)(k0 + j) * D_ + dd;
            KsT[dd * PAD + j] = K[g];
            Vs[j * DH + dd]   = V[g];
        }
        __syncthreads();

        // ---- phase 1: scores S = Q K^T ----
        float acc[4][8];
        #pragma unroll
        for (int i = 0; i < 4; i++)
            #pragma unroll
            for (int j = 0; j < 8; j++) acc[i][j] = 0.f;

        #pragma unroll 4
        for (int dd = 0; dd < DH; dd++) {
            float a[4], bb[8];
            #pragma unroll
            for (int i = 0; i < 4; i++) a[i] = QsT[dd * PAD + qg * 4 + i];
            #pragma unroll
            for (int j = 0; j < 8; j++) bb[j] = KsT[dd * PAD + jg * 8 + j];
            #pragma unroll
            for (int i = 0; i < 4; i++)
                #pragma unroll
                for (int j = 0; j < 8; j++)
                    acc[i][j] = fmaf(a[i], bb[j], acc[i][j]);
        }

        const bool diag = (kt == qt);
        #pragma unroll
        for (int i = 0; i < 4; i++) {
            int q = qg * 4 + i;
            #pragma unroll
            for (int j = 0; j < 8; j++) {
                int jj = jg * 8 + j;
                float s = acc[i][j];
                if (diag && jj > q) s = -1e30f;   // strict causal mask
                Ss[q * PAD + jj] = s;
            }
        }
        __syncthreads();

        // ---- phase 2: online softmax + PV ----
        const float* srow = Ss + qi * PAD;
        float mt = m;
        #pragma unroll 8
        for (int j = 0; j < KTILE; j++) mt = fmaxf(mt, srow[j]);

        float corr = __expf(m - mt);   // m=-1e30 initially -> corr=0 (safe)
        m = mt;
        l *= corr;
        #pragma unroll
        for (int i = 0; i < 32; i++) o[i] *= corr;

        const float* vbase = Vs + half * 32;
        for (int j = 0; j < KTILE; j++) {
            float p = __expf(srow[j] - mt);   // masked entries -> exp(-huge)=0
            l += p;
            const float4* v4 = (const float4*)(vbase + j * DH);
            #pragma unroll
            for (int i = 0; i < 8; i++) {
                float4 v = v4[i];
                o[i*4 + 0] = fmaf(p, v.x, o[i*4 + 0]);
                o[i*4 + 1] = fmaf(p, v.y, o[i*4 + 1]);
                o[i*4 + 2] = fmaf(p, v.z, o[i*4 + 2]);
                o[i*4 + 3] = fmaf(p, v.w, o[i*4 + 3]);
            }
        }
        __syncthreads();   // protect K/V/S smem before next tile's loads
    }

    const float inv = 1.f / l;
    float4* orow = (float4*)(O + base + (size_t)(q0 + qi) * D_ + half * 32);
    #pragma unroll
    for (int i = 0; i < 8; i++) {
        float4 v;
        v.x = o[i*4 + 0] * inv;
        v.y = o[i*4 + 1] * inv;
        v.z = o[i*4 + 2] * inv;
        v.w = o[i*4 + 3] * inv;
        orow[i] = v;
    }
}

// ---------------------------------------------------------------------------
extern "C" void kernel_launch(void* const* d_in, const int* in_sizes, int n_in,
                              void* d_out, int out_size)
{
    const float* x  = (const float*)d_in[0];
    const float* Wq = (const float*)d_in[1];
    const float* bq = (const float*)d_in[2];
    const float* Wk = (const float*)d_in[3];
    const float* bk = (const float*)d_in[4];
    const float* Wv = (const float*)d_in[5];
    const float* bv = (const float*)d_in[6];
    const float* Wo = (const float*)d_in[7];
    const float* bo = (const float*)d_in[8];
    float* out = (float*)d_out;

    float *Qp, *Kp, *Vp, *Ap;
    cudaGetSymbolAddress((void**)&Qp, g_Q);
    cudaGetSymbolAddress((void**)&Kp, g_K);
    cudaGetSymbolAddress((void**)&Vp, g_V);
    cudaGetSymbolAddress((void**)&Ap, g_A);

    const int smem_bytes = SMEM_FLOATS * (int)sizeof(float);
    cudaFuncSetAttribute(attn_kernel,
                         cudaFuncAttributeMaxDynamicSharedMemorySize, smem_bytes);

    dim3 ggrid(D_ / 64, M_ / 64);   // (16, 64)
    gemm_bias_kernel<<<ggrid, 256>>>(x, Wq, bq, Qp, M_, D_, D_);
    gemm_bias_kernel<<<ggrid, 256>>>(x, Wk, bk, Kp, M_, D_, D_);
    gemm_bias_kernel<<<ggrid, 256>>>(x, Wv, bv, Vp, M_, D_, D_);

    dim3 agrid(S_ / QTILE, H_, B_);  // (32, 16, 2)
    attn_kernel<<<agrid, 128, smem_bytes>>>(Qp, Kp, Vp, Ap);

    gemm_bias_kernel<<<ggrid, 256>>>(Ap, Wo, bo, out, M_, D_, D_);
}

// round 4
// speedup vs baseline: 1.3754x; 1.3754x over previous
#include <cuda_runtime.h>
#include <cuda_bf16.h>
#include <stdint.h>
#include <math.h>

#define B_  2
#define S_  2048
#define D_  1024
#define H_  16
#define DH  64
#define M_  (B_*S_)
#define DD  (D_*D_)
#define SCALE 0.03125f   // 1024^-0.5

// ---------------- scratch (__device__ globals: allocation-free rule) -------
__device__ float g_Q[M_*D_];
__device__ float g_K[M_*D_];
__device__ float g_V[M_*D_];
__device__ float g_A[M_*D_];
__device__ __nv_bfloat16 g_xh[M_*D_];
__device__ __nv_bfloat16 g_xl[M_*D_];
__device__ __nv_bfloat16 g_Ah[M_*D_];
__device__ __nv_bfloat16 g_Al[M_*D_];
// transposed split weights: [q_hi,q_lo,k_hi,k_lo,v_hi,v_lo,o_hi,o_lo] x [N=1024][K=1024]
__device__ __nv_bfloat16 g_WT[8*DD];

// ---------------- generic-PTX helpers (compute_103-safe) --------------------
__device__ __forceinline__ uint32_t smem_u32(const void* p) {
    uint32_t a;
    asm("{ .reg .u64 t; cvta.to.shared.u64 t, %1; cvt.u32.u64 %0, t; }"
        : "=r"(a) : "l"(p));
    return a;
}

__device__ __forceinline__ void cp_async16(uint32_t dst, const void* src) {
    asm volatile("cp.async.cg.shared.global [%0], [%1], 16;"
                 :: "r"(dst), "l"(src) : "memory");
}
__device__ __forceinline__ void cp_commit() {
    asm volatile("cp.async.commit_group;" ::: "memory");
}
template <int N>
__device__ __forceinline__ void cp_wait() {
    asm volatile("cp.async.wait_group %0;" :: "n"(N) : "memory");
}

__device__ __forceinline__ void ldsm4(uint32_t* r, uint32_t a) {
    asm volatile("ldmatrix.sync.aligned.m8n8.x4.shared.b16 {%0,%1,%2,%3}, [%4];"
                 : "=r"(r[0]), "=r"(r[1]), "=r"(r[2]), "=r"(r[3]) : "r"(a));
}
__device__ __forceinline__ void ldsm2(uint32_t* r, uint32_t a) {
    asm volatile("ldmatrix.sync.aligned.m8n8.x2.shared.b16 {%0,%1}, [%2];"
                 : "=r"(r[0]), "=r"(r[1]) : "r"(a));
}

__device__ __forceinline__ void mma16816(float* d, const uint32_t* a, const uint32_t* b) {
    asm volatile(
        "mma.sync.aligned.m16n8k16.row.col.f32.bf16.bf16.f32 "
        "{%0,%1,%2,%3}, {%4,%5,%6,%7}, {%8,%9}, {%0,%1,%2,%3};"
        : "+f"(d[0]), "+f"(d[1]), "+f"(d[2]), "+f"(d[3])
        : "r"(a[0]), "r"(a[1]), "r"(a[2]), "r"(a[3]), "r"(b[0]), "r"(b[1]));
}

// ---------------------------------------------------------------------------
// fp32 -> bf16 hi/lo split
// ---------------------------------------------------------------------------
__global__ __launch_bounds__(256) void split_kernel(
    const float* __restrict__ src,
    __nv_bfloat16* __restrict__ hi, __nv_bfloat16* __restrict__ lo)
{
    int i = (blockIdx.x * 256 + threadIdx.x) * 4;
    float4 v = *(const float4*)(src + i);
    __nv_bfloat16 h0 = __float2bfloat16(v.x);
    __nv_bfloat16 h1 = __float2bfloat16(v.y);
    __nv_bfloat16 h2 = __float2bfloat16(v.z);
    __nv_bfloat16 h3 = __float2bfloat16(v.w);
    __nv_bfloat162 a, b;
    a.x = h0; a.y = h1; b.x = h2; b.y = h3;
    *(__nv_bfloat162*)(hi + i)     = a;
    *(__nv_bfloat162*)(hi + i + 2) = b;
    __nv_bfloat162 c, d;
    c.x = __float2bfloat16(v.x - __bfloat162float(h0));
    c.y = __float2bfloat16(v.y - __bfloat162float(h1));
    d.x = __float2bfloat16(v.z - __bfloat162float(h2));
    d.y = __float2bfloat16(v.w - __bfloat162float(h3));
    *(__nv_bfloat162*)(lo + i)     = c;
    *(__nv_bfloat162*)(lo + i + 2) = d;
}

// ---------------------------------------------------------------------------
// weight transpose + split: W [K][N] row-major -> WT [N][K] bf16 hi/lo
// ---------------------------------------------------------------------------
__global__ __launch_bounds__(256) void transpose_split_kernel(
    const float* __restrict__ Wq, const float* __restrict__ Wk,
    const float* __restrict__ Wv, const float* __restrict__ Wo,
    __nv_bfloat16* __restrict__ out)
{
    __shared__ float tile[32][33];
    const int z = blockIdx.z;
    const float* W = (z == 0) ? Wq : (z == 1) ? Wk : (z == 2) ? Wv : Wo;
    __nv_bfloat16* hi = out + (size_t)(2 * z) * DD;
    __nv_bfloat16* lo = hi + DD;
    const int n0 = blockIdx.x * 32, k0 = blockIdx.y * 32;
    const int tx = threadIdx.x & 31, ty = threadIdx.x >> 5;

    #pragma unroll
    for (int j = 0; j < 4; j++)
        tile[ty + 8 * j][tx] = W[(size_t)(k0 + ty + 8 * j) * 1024 + n0 + tx];
    __syncthreads();
    #pragma unroll
    for (int j = 0; j < 4; j++) {
        int n = ty + 8 * j;
        float v = tile[tx][n];
        __nv_bfloat16 h = __float2bfloat16(v);
        size_t o = (size_t)(n0 + n) * 1024 + k0 + tx;
        hi[o] = h;
        lo[o] = __float2bfloat16(v - __bfloat162float(h));
    }
}

// ---------------------------------------------------------------------------
// mma.sync GEMM: C[128x128 tile] = Ah@Bh + Ah@Bl + Al@Bh + bias
//   A [M][1024] bf16 row-major (hi/lo);  WT [N][K] bf16 (= B col-major, hi/lo)
//   256 threads = 8 warps (2 m x 4 n), warp tile 64x32, BK=32, cp.async x2 buf
// smem tile: 128 rows x 32 halves, row stride 80 B (16B-aligned, LDSM
// conflict-free: row offsets mod 128B all distinct).
// ---------------------------------------------------------------------------
#define TILE_B   10240            // 128 * 80
#define STAGE_B  (4 * TILE_B)     // Ah,Al,Bh,Bl
#define GSMEM    (2 * STAGE_B)    // 81920

__global__ __launch_bounds__(256) void mma_gemm(
    const __nv_bfloat16* __restrict__ Ah,
    const __nv_bfloat16* __restrict__ Al,
    const __nv_bfloat16* __restrict__ WT,
    const float* bq, const float* bk, const float* bv, const float* bo,
    float* Cq, float* Ck, float* Cv, float* Co, int zoff)
{
    extern __shared__ unsigned char dynsm[];
    const uint32_t sbase = smem_u32(dynsm);
    const int t    = threadIdx.x;
    const int wid  = t >> 5;
    const int lane = t & 31;

    const int z = blockIdx.z + zoff;
    const float* bias = (z == 0) ? bq : (z == 1) ? bk : (z == 2) ? bv : bo;
    float* C          = (z == 0) ? Cq : (z == 1) ? Ck : (z == 2) ? Cv : Co;
    const __nv_bfloat16* Bh = WT + (size_t)(2 * z) * DD;
    const __nv_bfloat16* Bl = Bh + DD;

    const int row0 = blockIdx.y * 128;
    const int col0 = blockIdx.x * 128;
    const int warp_m = wid >> 2;          // 0..1 -> 64 rows
    const int warp_n = wid & 3;           // 0..3 -> 32 cols

    // ---- loader: 2048 x 16B chunks per stage, 8 per thread ----
    const __nv_bfloat16* gsrc[4] = { Ah, Al, Bh, Bl };
    const int grow0[4] = { row0, row0, col0, col0 };

    auto load_stage = [&](int stg, int c) {
        const uint32_t sb = sbase + stg * STAGE_B;
        #pragma unroll
        for (int i = 0; i < 8; i++) {
            int id   = t + i * 256;
            int tile = id >> 9;
            int rem  = id & 511;
            int r    = rem >> 2;
            int seg  = rem & 3;
            const __nv_bfloat16* src =
                gsrc[tile] + (size_t)(grow0[tile] + r) * 1024 + c * 32 + seg * 8;
            cp_async16(sb + tile * TILE_B + r * 80 + seg * 16, src);
        }
        cp_commit();
    };

    float acc[4][4][4];
    #pragma unroll
    for (int i = 0; i < 4; i++)
        #pragma unroll
        for (int j = 0; j < 4; j++)
            #pragma unroll
            for (int e = 0; e < 4; e++) acc[i][j][e] = 0.f;

    load_stage(0, 0);

    for (int c = 0; c < 32; c++) {
        if (c + 1 < 32) load_stage((c + 1) & 1, c + 1);
        if (c + 1 < 32) cp_wait<1>(); else cp_wait<0>();
        __syncthreads();

        const uint32_t sb  = sbase + (c & 1) * STAGE_B;
        const uint32_t aAh = sb;
        const uint32_t aAl = sb + TILE_B;
        const uint32_t aBh = sb + 2 * TILE_B;
        const uint32_t aBl = sb + 3 * TILE_B;

        #pragma unroll
        for (int ks = 0; ks < 2; ks++) {
            const uint32_t akb = ((lane >> 4) * 8 + ks * 16) * 2;          // A k-offset bytes
            const uint32_t arow = warp_m * 64 + (lane & 15);
            const uint32_t bkb = ((((lane >> 3) & 1) * 8) + ks * 16) * 2;  // B k-offset bytes
            const uint32_t brow = warp_n * 32 + (lane & 7);

            uint32_t ah[4][4], bh[4][2], bl[4][2];
            #pragma unroll
            for (int i = 0; i < 4; i++)
                ldsm4(ah[i], aAh + (arow + i * 16) * 80 + akb);
            #pragma unroll
            for (int j = 0; j < 4; j++) {
                ldsm2(bh[j], aBh + (brow + j * 8) * 80 + bkb);
                ldsm2(bl[j], aBl + (brow + j * 8) * 80 + bkb);
            }
            #pragma unroll
            for (int i = 0; i < 4; i++)
                #pragma unroll
                for (int j = 0; j < 4; j++)
                    mma16816(acc[i][j], ah[i], bh[j]);
            #pragma unroll
            for (int i = 0; i < 4; i++)
                #pragma unroll
                for (int j = 0; j < 4; j++)
                    mma16816(acc[i][j], ah[i], bl[j]);

            uint32_t al[4][4];
            #pragma unroll
            for (int i = 0; i < 4; i++)
                ldsm4(al[i], aAl + (arow + i * 16) * 80 + akb);
            #pragma unroll
            for (int i = 0; i < 4; i++)
                #pragma unroll
                for (int j = 0; j < 4; j++)
                    mma16816(acc[i][j], al[i], bh[j]);
        }
        __syncthreads();
    }

    // ---- epilogue: write C + bias ----
    const int gid = lane >> 2, tig = lane & 3;
    #pragma unroll
    for (int i = 0; i < 4; i++) {
        #pragma unroll
        for (int j = 0; j < 4; j++) {
            int r  = row0 + warp_m * 64 + i * 16 + gid;
            int cc = col0 + warp_n * 32 + j * 8 + tig * 2;
            float b0 = bias[cc], b1 = bias[cc + 1];
            float2 v0 = { acc[i][j][0] + b0, acc[i][j][1] + b1 };
            float2 v1 = { acc[i][j][2] + b0, acc[i][j][3] + b1 };
            *(float2*)(C + (size_t)r * 1024 + cc)       = v0;
            *(float2*)(C + (size_t)(r + 8) * 1024 + cc) = v1;
        }
    }
}

// ---------------------------------------------------------------------------
// Flash-attention (causal), fp32 — unchanged (proven correct).
// ---------------------------------------------------------------------------
#define QTILE 64
#define KTILE 64
#define PAD   68
#define SMEM_FLOATS (DH*PAD + DH*PAD + KTILE*DH + QTILE*PAD)

__global__ __launch_bounds__(128) void attn_kernel(
    const float* __restrict__ Q, const float* __restrict__ K,
    const float* __restrict__ V, float* __restrict__ O)
{
    extern __shared__ unsigned char dynsm[];
    float* smem = (float*)dynsm;
    float* QsT = smem;
    float* KsT = QsT + DH * PAD;
    float* Vs  = KsT + DH * PAD;
    float* Ss  = Vs  + KTILE * DH;

    const int t  = threadIdx.x;
    const int qt = blockIdx.x;
    const int h  = blockIdx.y;
    const int b  = blockIdx.z;

    const size_t base = (size_t)b * S_ * D_ + (size_t)h * DH;
    const int q0 = qt * QTILE;

    for (int idx = t; idx < QTILE * DH; idx += 128) {
        int q  = idx >> 6;
        int dd = idx & 63;
        QsT[dd * PAD + q] = Q[base + (size_t)(q0 + q) * D_ + dd] * SCALE;
    }

    const int qg = t >> 3;
    const int jg = t & 7;
    const int qi   = t >> 1;
    const int half = t & 1;

    float m = -1e30f, l = 0.f;
    float o[32];
    #pragma unroll
    for (int i = 0; i < 32; i++) o[i] = 0.f;

    __syncthreads();

    for (int kt = 0; kt <= qt; kt++) {
        const int k0 = kt * KTILE;

        for (int idx = t; idx < KTILE * DH; idx += 128) {
            int j  = idx >> 6;
            int dd = idx & 63;
            size_t g = base + (size_t)(k0 + j) * D_ + dd;
            KsT[dd * PAD + j] = K[g];
            Vs[j * DH + dd]   = V[g];
        }
        __syncthreads();

        float acc[4][8];
        #pragma unroll
        for (int i = 0; i < 4; i++)
            #pragma unroll
            for (int j = 0; j < 8; j++) acc[i][j] = 0.f;

        #pragma unroll 4
        for (int dd = 0; dd < DH; dd++) {
            float a[4], bb[8];
            #pragma unroll
            for (int i = 0; i < 4; i++) a[i] = QsT[dd * PAD + qg * 4 + i];
            #pragma unroll
            for (int j = 0; j < 8; j++) bb[j] = KsT[dd * PAD + jg * 8 + j];
            #pragma unroll
            for (int i = 0; i < 4; i++)
                #pragma unroll
                for (int j = 0; j < 8; j++)
                    acc[i][j] = fmaf(a[i], bb[j], acc[i][j]);
        }

        const bool diag = (kt == qt);
        #pragma unroll
        for (int i = 0; i < 4; i++) {
            int q = qg * 4 + i;
            #pragma unroll
            for (int j = 0; j < 8; j++) {
                int jj = jg * 8 + j;
                float s = acc[i][j];
                if (diag && jj > q) s = -1e30f;
                Ss[q * PAD + jj] = s;
            }
        }
        __syncthreads();

        const float* srow = Ss + qi * PAD;
        float mt = m;
        #pragma unroll 8
        for (int j = 0; j < KTILE; j++) mt = fmaxf(mt, srow[j]);

        float corr = __expf(m - mt);
        m = mt;
        l *= corr;
        #pragma unroll
        for (int i = 0; i < 32; i++) o[i] *= corr;

        const float* vbase = Vs + half * 32;
        for (int j = 0; j < KTILE; j++) {
            float p = __expf(srow[j] - mt);
            l += p;
            const float4* v4 = (const float4*)(vbase + j * DH);
            #pragma unroll
            for (int i = 0; i < 8; i++) {
                float4 v = v4[i];
                o[i*4 + 0] = fmaf(p, v.x, o[i*4 + 0]);
                o[i*4 + 1] = fmaf(p, v.y, o[i*4 + 1]);
                o[i*4 + 2] = fmaf(p, v.z, o[i*4 + 2]);
                o[i*4 + 3] = fmaf(p, v.w, o[i*4 + 3]);
            }
        }
        __syncthreads();
    }

    const float inv = 1.f / l;
    float4* orow = (float4*)(O + base + (size_t)(q0 + qi) * D_ + half * 32);
    #pragma unroll
    for (int i = 0; i < 8; i++) {
        float4 v;
        v.x = o[i*4 + 0] * inv;
        v.y = o[i*4 + 1] * inv;
        v.z = o[i*4 + 2] * inv;
        v.w = o[i*4 + 3] * inv;
        orow[i] = v;
    }
}

// ---------------------------------------------------------------------------
extern "C" void kernel_launch(void* const* d_in, const int* in_sizes, int n_in,
                              void* d_out, int out_size)
{
    const float* x  = (const float*)d_in[0];
    const float* Wq = (const float*)d_in[1];
    const float* bq = (const float*)d_in[2];
    const float* Wk = (const float*)d_in[3];
    const float* bk = (const float*)d_in[4];
    const float* Wv = (const float*)d_in[5];
    const float* bv = (const float*)d_in[6];
    const float* Wo = (const float*)d_in[7];
    const float* bo = (const float*)d_in[8];
    float* out = (float*)d_out;

    float *Qp, *Kp, *Vp, *Ap;
    __nv_bfloat16 *xh, *xl, *Ahp, *Alp, *WTp;
    cudaGetSymbolAddress((void**)&Qp, g_Q);
    cudaGetSymbolAddress((void**)&Kp, g_K);
    cudaGetSymbolAddress((void**)&Vp, g_V);
    cudaGetSymbolAddress((void**)&Ap, g_A);
    cudaGetSymbolAddress((void**)&xh, g_xh);
    cudaGetSymbolAddress((void**)&xl, g_xl);
    cudaGetSymbolAddress((void**)&Ahp, g_Ah);
    cudaGetSymbolAddress((void**)&Alp, g_Al);
    cudaGetSymbolAddress((void**)&WTp, g_WT);

    cudaFuncSetAttribute(mma_gemm,
                         cudaFuncAttributeMaxDynamicSharedMemorySize, GSMEM);
    const int attn_smem = SMEM_FLOATS * (int)sizeof(float);
    cudaFuncSetAttribute(attn_kernel,
                         cudaFuncAttributeMaxDynamicSharedMemorySize, attn_smem);

    // 1. split x into bf16 hi/lo
    split_kernel<<<M_ * D_ / 1024, 256>>>(x, xh, xl);
    // 2. transpose + split all four weights
    transpose_split_kernel<<<dim3(32, 32, 4), 256>>>(Wq, Wk, Wv, Wo, WTp);
    // 3. fused Q/K/V projections on tensor cores (mma.sync)
    mma_gemm<<<dim3(8, 32, 3), 256, GSMEM>>>(
        xh, xl, WTp, bq, bk, bv, bo, Qp, Kp, Vp, out, 0);
    // 4. causal attention (fp32)
    attn_kernel<<<dim3(S_ / QTILE, H_, B_), 128, attn_smem>>>(Qp, Kp, Vp, Ap);
    // 5. split attention output
    split_kernel<<<M_ * D_ / 1024, 256>>>(Ap, Ahp, Alp);
    // 6. output projection -> d_out
    mma_gemm<<<dim3(8, 32, 1), 256, GSMEM>>>(
        Ahp, Alp, WTp, bq, bk, bv, bo, Qp, Kp, Vp, out, 3);
}

// round 5
// speedup vs baseline: 3.6513x; 2.6548x over previous
#include <cuda_runtime.h>
#include <cuda_fp16.h>
#include <stdint.h>
#include <math.h>

#define B_  2
#define S_  2048
#define D_  1024
#define H_  16
#define DH  64
#define M_  (B_*S_)
#define DD  (D_*D_)
#define SCALE2 0.045084439f   // 1024^-0.5 * log2(e)

// ---------------- scratch (__device__ globals: allocation-free rule) -------
__device__ __half g_xh[M_*D_];
__device__ __half g_xl[M_*D_];
__device__ __half g_Qh[M_*D_];
__device__ __half g_Ql[M_*D_];
__device__ __half g_Kh[M_*D_];
__device__ __half g_Kl[M_*D_];
__device__ __half g_Vh[M_*D_];
__device__ __half g_Vl[M_*D_];
__device__ __half g_Ah[M_*D_];
__device__ __half g_Al[M_*D_];
// transposed split weights: [q_hi,q_lo,k_hi,k_lo,v_hi,v_lo,o_hi,o_lo] x [N][K]
__device__ __half g_WT[8*DD];

// ---------------- generic-PTX helpers (compute_103-safe) -------------------
__device__ __forceinline__ uint32_t smem_u32(const void* p) {
    uint32_t a;
    asm("{ .reg .u64 t; cvta.to.shared.u64 t, %1; cvt.u32.u64 %0, t; }"
        : "=r"(a) : "l"(p));
    return a;
}
__device__ __forceinline__ void cp_async16(uint32_t dst, const void* src) {
    asm volatile("cp.async.cg.shared.global [%0], [%1], 16;"
                 :: "r"(dst), "l"(src) : "memory");
}
__device__ __forceinline__ void cp_commit() {
    asm volatile("cp.async.commit_group;" ::: "memory");
}
template <int N>
__device__ __forceinline__ void cp_wait() {
    asm volatile("cp.async.wait_group %0;" :: "n"(N) : "memory");
}
__device__ __forceinline__ void ldsm4(uint32_t* r, uint32_t a) {
    asm volatile("ldmatrix.sync.aligned.m8n8.x4.shared.b16 {%0,%1,%2,%3}, [%4];"
                 : "=r"(r[0]), "=r"(r[1]), "=r"(r[2]), "=r"(r[3]) : "r"(a));
}
__device__ __forceinline__ void ldsm4t(uint32_t* r, uint32_t a) {
    asm volatile("ldmatrix.sync.aligned.m8n8.x4.trans.shared.b16 {%0,%1,%2,%3}, [%4];"
                 : "=r"(r[0]), "=r"(r[1]), "=r"(r[2]), "=r"(r[3]) : "r"(a));
}
__device__ __forceinline__ void ldsm2(uint32_t* r, uint32_t a) {
    asm volatile("ldmatrix.sync.aligned.m8n8.x2.shared.b16 {%0,%1}, [%2];"
                 : "=r"(r[0]), "=r"(r[1]) : "r"(a));
}
__device__ __forceinline__ void mma16816(float* d, const uint32_t* a,
                                         uint32_t b0, uint32_t b1) {
    asm volatile(
        "mma.sync.aligned.m16n8k16.row.col.f32.f16.f16.f32 "
        "{%0,%1,%2,%3}, {%4,%5,%6,%7}, {%8,%9}, {%0,%1,%2,%3};"
        : "+f"(d[0]), "+f"(d[1]), "+f"(d[2]), "+f"(d[3])
        : "r"(a[0]), "r"(a[1]), "r"(a[2]), "r"(a[3]), "r"(b0), "r"(b1));
}
__device__ __forceinline__ uint32_t packh2(float a, float b) {
    __half2 h = __floats2half2_rn(a, b);
    return *(uint32_t*)&h;
}
__device__ __forceinline__ float2 h2f2(uint32_t u) {
    __half2 h = *(__half2*)&u;
    return __half22float2(h);
}

// ---------------------------------------------------------------------------
// fp32 -> fp16 hi/lo split (for x)
// ---------------------------------------------------------------------------
__global__ __launch_bounds__(256) void split_kernel(
    const float* __restrict__ src,
    __half* __restrict__ hi, __half* __restrict__ lo)
{
    int i = (blockIdx.x * 256 + threadIdx.x) * 4;
    float4 v = *(const float4*)(src + i);
    __half h0 = __float2half_rn(v.x), h1 = __float2half_rn(v.y);
    __half h2 = __float2half_rn(v.z), h3 = __float2half_rn(v.w);
    __half2 a; a.x = h0; a.y = h1;
    __half2 b; b.x = h2; b.y = h3;
    *(__half2*)(hi + i)     = a;
    *(__half2*)(hi + i + 2) = b;
    __half2 c, d;
    c.x = __float2half_rn(v.x - __half2float(h0));
    c.y = __float2half_rn(v.y - __half2float(h1));
    d.x = __float2half_rn(v.z - __half2float(h2));
    d.y = __float2half_rn(v.w - __half2float(h3));
    *(__half2*)(lo + i)     = c;
    *(__half2*)(lo + i + 2) = d;
}

// ---------------------------------------------------------------------------
// weight transpose + split: W [K][N] row-major -> WT [N][K] fp16 hi/lo
// ---------------------------------------------------------------------------
__global__ __launch_bounds__(256) void transpose_split_kernel(
    const float* __restrict__ Wq, const float* __restrict__ Wk,
    const float* __restrict__ Wv, const float* __restrict__ Wo,
    __half* __restrict__ out)
{
    __shared__ float tile[32][33];
    const int z = blockIdx.z;
    const float* W = (z == 0) ? Wq : (z == 1) ? Wk : (z == 2) ? Wv : Wo;
    __half* hi = out + (size_t)(2 * z) * DD;
    __half* lo = hi + DD;
    const int n0 = blockIdx.x * 32, k0 = blockIdx.y * 32;
    const int tx = threadIdx.x & 31, ty = threadIdx.x >> 5;

    #pragma unroll
    for (int j = 0; j < 4; j++)
        tile[ty + 8 * j][tx] = W[(size_t)(k0 + ty + 8 * j) * 1024 + n0 + tx];
    __syncthreads();
    #pragma unroll
    for (int j = 0; j < 4; j++) {
        int n = ty + 8 * j;
        float v = tile[tx][n];
        __half h = __float2half_rn(v);
        size_t o = (size_t)(n0 + n) * 1024 + k0 + tx;
        hi[o] = h;
        lo[o] = __float2half_rn(v - __half2float(h));
    }
}

// ---------------------------------------------------------------------------
// mma.sync GEMM: C = Ah@Bh + Ah@Bl + Al@Bh + bias
//   z=0: -> (Qh,Ql) scaled by SCALE2;  z=1: -> (Kh,Kl);  z=2: -> (Vh,Vl)
//   z=3: -> fp32 out
// ---------------------------------------------------------------------------
#define TILE_B   10240            // 128 * 80
#define STAGE_B  (4 * TILE_B)
#define GSMEM    (2 * STAGE_B)

__global__ __launch_bounds__(256) void mma_gemm(
    const __half* __restrict__ Ain_h,
    const __half* __restrict__ Ain_l,
    const __half* __restrict__ WT,
    const float* bq, const float* bk, const float* bv, const float* bo,
    __half* Qh, __half* Ql, __half* Kh, __half* Kl, __half* Vh, __half* Vl,
    float* outF, int zoff)
{
    extern __shared__ unsigned char dynsm[];
    const uint32_t sbase = smem_u32(dynsm);
    const int t    = threadIdx.x;
    const int wid  = t >> 5;
    const int lane = t & 31;

    const int z = blockIdx.z + zoff;
    const float* bias = (z == 0) ? bq : (z == 1) ? bk : (z == 2) ? bv : bo;
    const __half* Bh = WT + (size_t)(2 * z) * DD;
    const __half* Bl = Bh + DD;

    const int row0 = blockIdx.y * 128;
    const int col0 = blockIdx.x * 128;
    const int warp_m = wid >> 2;
    const int warp_n = wid & 3;

    const __half* gsrc[4] = { Ain_h, Ain_l, Bh, Bl };
    const int grow0[4] = { row0, row0, col0, col0 };

    auto load_stage = [&](int stg, int c) {
        const uint32_t sb = sbase + stg * STAGE_B;
        #pragma unroll
        for (int i = 0; i < 8; i++) {
            int id   = t + i * 256;
            int tile = id >> 9;
            int rem  = id & 511;
            int r    = rem >> 2;
            int seg  = rem & 3;
            const __half* src =
                gsrc[tile] + (size_t)(grow0[tile] + r) * 1024 + c * 32 + seg * 8;
            cp_async16(sb + tile * TILE_B + r * 80 + seg * 16, src);
        }
        cp_commit();
    };

    float acc[4][4][4];
    #pragma unroll
    for (int i = 0; i < 4; i++)
        #pragma unroll
        for (int j = 0; j < 4; j++)
            #pragma unroll
            for (int e = 0; e < 4; e++) acc[i][j][e] = 0.f;

    load_stage(0, 0);

    for (int c = 0; c < 32; c++) {
        if (c + 1 < 32) { load_stage((c + 1) & 1, c + 1); cp_wait<1>(); }
        else            { cp_wait<0>(); }
        __syncthreads();

        const uint32_t sb  = sbase + (c & 1) * STAGE_B;
        const uint32_t aAh = sb;
        const uint32_t aAl = sb + TILE_B;
        const uint32_t aBh = sb + 2 * TILE_B;
        const uint32_t aBl = sb + 3 * TILE_B;

        #pragma unroll
        for (int ks = 0; ks < 2; ks++) {
            const uint32_t akb  = ((lane >> 4) * 8 + ks * 16) * 2;
            const uint32_t arow = warp_m * 64 + (lane & 15);
            const uint32_t bkb  = ((((lane >> 3) & 1) * 8) + ks * 16) * 2;
            const uint32_t brow = warp_n * 32 + (lane & 7);

            uint32_t ah[4][4], bh[4][2], bl[4][2];
            #pragma unroll
            for (int i = 0; i < 4; i++)
                ldsm4(ah[i], aAh + (arow + i * 16) * 80 + akb);
            #pragma unroll
            for (int j = 0; j < 4; j++) {
                ldsm2(bh[j], aBh + (brow + j * 8) * 80 + bkb);
                ldsm2(bl[j], aBl + (brow + j * 8) * 80 + bkb);
            }
            #pragma unroll
            for (int i = 0; i < 4; i++)
                #pragma unroll
                for (int j = 0; j < 4; j++)
                    mma16816(acc[i][j], ah[i], bh[j][0], bh[j][1]);
            #pragma unroll
            for (int i = 0; i < 4; i++)
                #pragma unroll
                for (int j = 0; j < 4; j++)
                    mma16816(acc[i][j], ah[i], bl[j][0], bl[j][1]);

            uint32_t al[4][4];
            #pragma unroll
            for (int i = 0; i < 4; i++)
                ldsm4(al[i], aAl + (arow + i * 16) * 80 + akb);
            #pragma unroll
            for (int i = 0; i < 4; i++)
                #pragma unroll
                for (int j = 0; j < 4; j++)
                    mma16816(acc[i][j], al[i], bh[j][0], bh[j][1]);
        }
        __syncthreads();
    }

    // ---- epilogue ----
    const int gid = lane >> 2, tig = lane & 3;
    __half* OH = (z == 0) ? Qh : (z == 1) ? Kh : Vh;
    __half* OL = (z == 0) ? Ql : (z == 1) ? Kl : Vl;
    const float sc = (z == 0) ? SCALE2 : 1.0f;

    #pragma unroll
    for (int i = 0; i < 4; i++) {
        #pragma unroll
        for (int j = 0; j < 4; j++) {
            int r  = row0 + warp_m * 64 + i * 16 + gid;
            int cc = col0 + warp_n * 32 + j * 8 + tig * 2;
            float b0 = bias[cc], b1 = bias[cc + 1];
            float v00 = acc[i][j][0] + b0, v01 = acc[i][j][1] + b1;
            float v10 = acc[i][j][2] + b0, v11 = acc[i][j][3] + b1;
            if (z == 3) {
                float2 a = { v00, v01 }, b = { v10, v11 };
                *(float2*)(outF + (size_t)r * 1024 + cc)       = a;
                *(float2*)(outF + (size_t)(r + 8) * 1024 + cc) = b;
            } else {
                v00 *= sc; v01 *= sc; v10 *= sc; v11 *= sc;
                uint32_t h0 = packh2(v00, v01);
                uint32_t h1 = packh2(v10, v11);
                float2 f0 = h2f2(h0), f1 = h2f2(h1);
                uint32_t l0 = packh2(v00 - f0.x, v01 - f0.y);
                uint32_t l1 = packh2(v10 - f1.x, v11 - f1.y);
                *(uint32_t*)(OH + (size_t)r * 1024 + cc)       = h0;
                *(uint32_t*)(OH + (size_t)(r + 8) * 1024 + cc) = h1;
                *(uint32_t*)(OL + (size_t)r * 1024 + cc)       = l0;
                *(uint32_t*)(OL + (size_t)(r + 8) * 1024 + cc) = l1;
            }
        }
    }
}

// ---------------------------------------------------------------------------
// Tensor-core flash attention (causal), split-fp16 3-pass, log2-domain softmax.
// CTA: (q-tile of 128, head, batch). 4 warps; warp = 32 q-rows x full width.
// ---------------------------------------------------------------------------
#define AT_PADB 144                    // smem row stride bytes (72 halves)
#define AQ_BYTES (128 * AT_PADB)       // 18432 per Q matrix
#define AKV_BYTES (64 * AT_PADB)       // 9216 per K/V matrix
#define AT_STAGE (4 * AKV_BYTES)       // Kh,Kl,Vh,Vl = 36864
#define AT_SMEM (2 * AQ_BYTES + 2 * AT_STAGE)   // 110592

__global__ __launch_bounds__(128) void attn_mma_kernel(
    const __half* __restrict__ Qh, const __half* __restrict__ Ql,
    const __half* __restrict__ Kh, const __half* __restrict__ Kl,
    const __half* __restrict__ Vh, const __half* __restrict__ Vl,
    __half* __restrict__ Ah, __half* __restrict__ Al)
{
    extern __shared__ unsigned char dynsm[];
    const uint32_t sbase = smem_u32(dynsm);
    const uint32_t sQh = sbase;
    const uint32_t sQl = sbase + AQ_BYTES;
    const uint32_t sKV = sbase + 2 * AQ_BYTES;

    const int t    = threadIdx.x;
    const int wid  = t >> 5;
    const int lane = t & 31;
    const int qi   = (int)gridDim.x - 1 - (int)blockIdx.x;  // big tiles first
    const int hd   = blockIdx.y;
    const int bb   = blockIdx.z;
    const int q0   = qi * 128;
    const int nkt  = 2 * qi + 2;
    const int m0   = wid * 32;

    const size_t base = (size_t)bb * S_ * D_ + (size_t)hd * DH;

    // ---- prologue loads: Q (both) + KV stage 0, one commit group ----
    {
        #pragma unroll
        for (int i = 0; i < 16; i++) {
            int id  = t + i * 128;
            int mat = id >> 10;
            int rem = id & 1023;
            int r   = rem >> 3;
            int seg = rem & 7;
            const __half* src = (mat == 0 ? Qh : Ql) + base + (size_t)(q0 + r) * D_ + seg * 8;
            cp_async16((mat == 0 ? sQh : sQl) + r * AT_PADB + seg * 16, src);
        }
    }
    auto load_kv = [&](int stg, int k0) {
        const uint32_t sb = sKV + stg * AT_STAGE;
        const __half* srcs[4] = { Kh, Kl, Vh, Vl };
        #pragma unroll
        for (int i = 0; i < 16; i++) {
            int id  = t + i * 128;
            int mat = id >> 9;
            int rem = id & 511;
            int r   = rem >> 3;
            int seg = rem & 7;
            const __half* src = srcs[mat] + base + (size_t)(k0 + r) * D_ + seg * 8;
            cp_async16(sb + mat * AKV_BYTES + r * AT_PADB + seg * 16, src);
        }
        cp_commit();
    };
    load_kv(0, 0);   // commits group containing Q + stage0

    float s[2][8][4];
    float o[2][8][4];
    float mrun[2][2], lrun[2][2];
    #pragma unroll
    for (int ma = 0; ma < 2; ma++) {
        #pragma unroll
        for (int n = 0; n < 8; n++)
            #pragma unroll
            for (int e = 0; e < 4; e++) o[ma][n][e] = 0.f;
        mrun[ma][0] = mrun[ma][1] = -1e30f;
        lrun[ma][0] = lrun[ma][1] = 0.f;
    }

    for (int kt = 0; kt < nkt; kt++) {
        const int k0 = kt * 64;
        if (kt + 1 < nkt) { load_kv((kt + 1) & 1, (kt + 1) * 64); cp_wait<1>(); }
        else              { cp_wait<0>(); }
        __syncthreads();

        const uint32_t stg = sKV + (kt & 1) * AT_STAGE;
        const uint32_t tKh = stg;
        const uint32_t tKl = stg + AKV_BYTES;
        const uint32_t tVh = stg + 2 * AKV_BYTES;
        const uint32_t tVl = stg + 3 * AKV_BYTES;

        // ---- S = Q K^T (3-pass) ----
        #pragma unroll
        for (int ma = 0; ma < 2; ma++)
            #pragma unroll
            for (int n = 0; n < 8; n++)
                #pragma unroll
                for (int e = 0; e < 4; e++) s[ma][n][e] = 0.f;

        #pragma unroll
        for (int ks = 0; ks < 4; ks++) {
            const uint32_t colb = ks * 32 + (lane >> 4) * 16;
            uint32_t ah[2][4], al[2][4];
            #pragma unroll
            for (int ma = 0; ma < 2; ma++) {
                uint32_t roff = (m0 + ma * 16 + (lane & 15)) * AT_PADB + colb;
                ldsm4(ah[ma], sQh + roff);
                ldsm4(al[ma], sQl + roff);
            }
            uint32_t kh[4][4], kl[4][4];
            #pragma unroll
            for (int g = 0; g < 4; g++) {
                uint32_t roff = (g * 16 + (lane & 15)) * AT_PADB + colb;
                ldsm4(kh[g], tKh + roff);
                ldsm4(kl[g], tKl + roff);
            }
            #pragma unroll
            for (int ma = 0; ma < 2; ma++)
                #pragma unroll
                for (int n = 0; n < 8; n++) {
                    int g = n >> 1, odd = n & 1;
                    mma16816(s[ma][n], ah[ma], kh[g][odd], kh[g][odd + 2]);
                }
            #pragma unroll
            for (int ma = 0; ma < 2; ma++)
                #pragma unroll
                for (int n = 0; n < 8; n++) {
                    int g = n >> 1, odd = n & 1;
                    mma16816(s[ma][n], ah[ma], kl[g][odd], kl[g][odd + 2]);
                }
            #pragma unroll
            for (int ma = 0; ma < 2; ma++)
                #pragma unroll
                for (int n = 0; n < 8; n++) {
                    int g = n >> 1, odd = n & 1;
                    mma16816(s[ma][n], al[ma], kh[g][odd], kh[g][odd + 2]);
                }
        }

        // ---- causal mask (only tiles touching the diagonal) ----
        if (k0 + 63 > q0 + m0) {
            #pragma unroll
            for (int ma = 0; ma < 2; ma++)
                #pragma unroll
                for (int n = 0; n < 8; n++)
                    #pragma unroll
                    for (int e = 0; e < 4; e++) {
                        int row = q0 + m0 + ma * 16 + (lane >> 2) + (e >> 1) * 8;
                        int col = k0 + n * 8 + (lane & 3) * 2 + (e & 1);
                        if (col > row) s[ma][n][e] = -1e30f;
                    }
        }

        // ---- online softmax (log2 domain) ----
        #pragma unroll
        for (int ma = 0; ma < 2; ma++) {
            #pragma unroll
            for (int hh = 0; hh < 2; hh++) {
                float mx = -1e30f;
                #pragma unroll
                for (int n = 0; n < 8; n++)
                    mx = fmaxf(mx, fmaxf(s[ma][n][2 * hh], s[ma][n][2 * hh + 1]));
                mx = fmaxf(mx, __shfl_xor_sync(0xffffffffu, mx, 1));
                mx = fmaxf(mx, __shfl_xor_sync(0xffffffffu, mx, 2));
                float mnew = fmaxf(mrun[ma][hh], mx);
                float corr = exp2f(mrun[ma][hh] - mnew);
                mrun[ma][hh] = mnew;
                float ls = 0.f;
                #pragma unroll
                for (int n = 0; n < 8; n++) {
                    float p0 = exp2f(s[ma][n][2 * hh]     - mnew);
                    float p1 = exp2f(s[ma][n][2 * hh + 1] - mnew);
                    s[ma][n][2 * hh]     = p0;
                    s[ma][n][2 * hh + 1] = p1;
                    ls += p0 + p1;
                    o[ma][n][2 * hh]     *= corr;
                    o[ma][n][2 * hh + 1] *= corr;
                }
                ls += __shfl_xor_sync(0xffffffffu, ls, 1);
                ls += __shfl_xor_sync(0xffffffffu, ls, 2);
                lrun[ma][hh] = lrun[ma][hh] * corr + ls;
            }
        }

        // ---- O += P V (3-pass) ----
        #pragma unroll
        for (int ks = 0; ks < 4; ks++) {
            uint32_t aph[2][4], apl[2][4];
            #pragma unroll
            for (int ma = 0; ma < 2; ma++) {
                float p00 = s[ma][2*ks][0],   p01 = s[ma][2*ks][1];
                float p02 = s[ma][2*ks][2],   p03 = s[ma][2*ks][3];
                float p10 = s[ma][2*ks+1][0], p11 = s[ma][2*ks+1][1];
                float p12 = s[ma][2*ks+1][2], p13 = s[ma][2*ks+1][3];
                aph[ma][0] = packh2(p00, p01);
                aph[ma][1] = packh2(p02, p03);
                aph[ma][2] = packh2(p10, p11);
                aph[ma][3] = packh2(p12, p13);
                float2 f0 = h2f2(aph[ma][0]), f1 = h2f2(aph[ma][1]);
                float2 f2 = h2f2(aph[ma][2]), f3 = h2f2(aph[ma][3]);
                apl[ma][0] = packh2(p00 - f0.x, p01 - f0.y);
                apl[ma][1] = packh2(p02 - f1.x, p03 - f1.y);
                apl[ma][2] = packh2(p10 - f2.x, p11 - f2.y);
                apl[ma][3] = packh2(p12 - f3.x, p13 - f3.y);
            }
            uint32_t vh[4][4], vl[4][4];
            const int g = lane >> 3, li = lane & 7;
            #pragma unroll
            for (int nb = 0; nb < 4; nb++) {
                uint32_t roff = (uint32_t)(ks * 16 + (g & 1) * 8 + li) * AT_PADB
                              + (nb * 16 + (g >> 1) * 8) * 2;
                ldsm4t(vh[nb], tVh + roff);
                ldsm4t(vl[nb], tVl + roff);
            }
            #pragma unroll
            for (int ma = 0; ma < 2; ma++)
                #pragma unroll
                for (int n = 0; n < 8; n++) {
                    int nb = n >> 1, odd = (n & 1) * 2;
                    mma16816(o[ma][n], aph[ma], vh[nb][odd], vh[nb][odd + 1]);
                }
            #pragma unroll
            for (int ma = 0; ma < 2; ma++)
                #pragma unroll
                for (int n = 0; n < 8; n++) {
                    int nb = n >> 1, odd = (n & 1) * 2;
                    mma16816(o[ma][n], apl[ma], vh[nb][odd], vh[nb][odd + 1]);
                }
            #pragma unroll
            for (int ma = 0; ma < 2; ma++)
                #pragma unroll
                for (int n = 0; n < 8; n++) {
                    int nb = n >> 1, odd = (n & 1) * 2;
                    mma16816(o[ma][n], aph[ma], vl[nb][odd], vl[nb][odd + 1]);
                }
        }
        __syncthreads();
    }

    // ---- epilogue: normalize, split to half hi/lo for the Wo GEMM ----
    #pragma unroll
    for (int ma = 0; ma < 2; ma++) {
        float inv0 = 1.f / lrun[ma][0];
        float inv1 = 1.f / lrun[ma][1];
        int r0 = q0 + m0 + ma * 16 + (lane >> 2);
        #pragma unroll
        for (int n = 0; n < 8; n++) {
            int cc = hd * 64 + n * 8 + (lane & 3) * 2;
            float v00 = o[ma][n][0] * inv0, v01 = o[ma][n][1] * inv0;
            float v10 = o[ma][n][2] * inv1, v11 = o[ma][n][3] * inv1;
            uint32_t h0 = packh2(v00, v01);
            uint32_t h1 = packh2(v10, v11);
            float2 f0 = h2f2(h0), f1 = h2f2(h1);
            uint32_t l0 = packh2(v00 - f0.x, v01 - f0.y);
            uint32_t l1 = packh2(v10 - f1.x, v11 - f1.y);
            size_t a0 = (size_t)(bb * S_ + r0) * D_ + cc;
            size_t a1 = (size_t)(bb * S_ + r0 + 8) * D_ + cc;
            *(uint32_t*)(Ah + a0) = h0;
            *(uint32_t*)(Ah + a1) = h1;
            *(uint32_t*)(Al + a0) = l0;
            *(uint32_t*)(Al + a1) = l1;
        }
    }
}

// ---------------------------------------------------------------------------
extern "C" void kernel_launch(void* const* d_in, const int* in_sizes, int n_in,
                              void* d_out, int out_size)
{
    const float* x  = (const float*)d_in[0];
    const float* Wq = (const float*)d_in[1];
    const float* bq = (const float*)d_in[2];
    const float* Wk = (const float*)d_in[3];
    const float* bk = (const float*)d_in[4];
    const float* Wv = (const float*)d_in[5];
    const float* bv = (const float*)d_in[6];
    const float* Wo = (const float*)d_in[7];
    const float* bo = (const float*)d_in[8];
    float* out = (float*)d_out;

    __half *xh, *xl, *Qh, *Ql, *Kh, *Kl, *Vh, *Vl, *Ahp, *Alp, *WTp;
    cudaGetSymbolAddress((void**)&xh,  g_xh);
    cudaGetSymbolAddress((void**)&xl,  g_xl);
    cudaGetSymbolAddress((void**)&Qh,  g_Qh);
    cudaGetSymbolAddress((void**)&Ql,  g_Ql);
    cudaGetSymbolAddress((void**)&Kh,  g_Kh);
    cudaGetSymbolAddress((void**)&Kl,  g_Kl);
    cudaGetSymbolAddress((void**)&Vh,  g_Vh);
    cudaGetSymbolAddress((void**)&Vl,  g_Vl);
    cudaGetSymbolAddress((void**)&Ahp, g_Ah);
    cudaGetSymbolAddress((void**)&Alp, g_Al);
    cudaGetSymbolAddress((void**)&WTp, g_WT);

    cudaFuncSetAttribute(mma_gemm,
                         cudaFuncAttributeMaxDynamicSharedMemorySize, GSMEM);
    cudaFuncSetAttribute(attn_mma_kernel,
                         cudaFuncAttributeMaxDynamicSharedMemorySize, AT_SMEM);

    // 1. split x into fp16 hi/lo
    split_kernel<<<M_ * D_ / 1024, 256>>>(x, xh, xl);
    // 2. transpose + split all four weights
    transpose_split_kernel<<<dim3(32, 32, 4), 256>>>(Wq, Wk, Wv, Wo, WTp);
    // 3. fused Q/K/V projections -> split fp16 outputs (Q pre-scaled)
    mma_gemm<<<dim3(8, 32, 3), 256, GSMEM>>>(
        xh, xl, WTp, bq, bk, bv, bo, Qh, Ql, Kh, Kl, Vh, Vl, out, 0);
    // 4. tensor-core causal attention -> split fp16 output
    attn_mma_kernel<<<dim3(S_ / 128, H_, B_), 128, AT_SMEM>>>(
        Qh, Ql, Kh, Kl, Vh, Vl, Ahp, Alp);
    // 5. output projection -> d_out (fp32)
    mma_gemm<<<dim3(8, 32, 1), 256, GSMEM>>>(
        Ahp, Alp, WTp, bq, bk, bv, bo, Qh, Ql, Kh, Kl, Vh, Vl, out, 3);
}

// round 6
// speedup vs baseline: 4.7174x; 1.2920x over previous
#include <cuda_runtime.h>
#include <cuda_fp16.h>
#include <stdint.h>
#include <math.h>

#define B_  2
#define S_  2048
#define D_  1024
#define H_  16
#define DH  64
#define M_  (B_*S_)
#define DD  (D_*D_)
#define SCALE2 0.045084439f   // 1024^-0.5 * log2(e)

// ---------------- scratch (__device__ globals: allocation-free rule) -------
__device__ __half g_xh[M_*D_];
__device__ __half g_xl[M_*D_];
__device__ __half g_Qh[M_*D_];
__device__ __half g_Ql[M_*D_];
__device__ __half g_Kh[M_*D_];
__device__ __half g_Vh[M_*D_];
__device__ __half g_Vl[M_*D_];
__device__ __half g_Ah[M_*D_];
__device__ __half g_Al[M_*D_];
// transposed weights (hi only): [q,k,v,o] x [N][K]
__device__ __half g_WT[4*DD];

// ---------------- generic-PTX helpers (compute_103-safe) -------------------
__device__ __forceinline__ uint32_t smem_u32(const void* p) {
    uint32_t a;
    asm("{ .reg .u64 t; cvta.to.shared.u64 t, %1; cvt.u32.u64 %0, t; }"
        : "=r"(a) : "l"(p));
    return a;
}
__device__ __forceinline__ void cp_async16(uint32_t dst, const void* src) {
    asm volatile("cp.async.cg.shared.global [%0], [%1], 16;"
                 :: "r"(dst), "l"(src) : "memory");
}
__device__ __forceinline__ void cp_commit() {
    asm volatile("cp.async.commit_group;" ::: "memory");
}
template <int N>
__device__ __forceinline__ void cp_wait() {
    asm volatile("cp.async.wait_group %0;" :: "n"(N) : "memory");
}
__device__ __forceinline__ void ldsm4(uint32_t* r, uint32_t a) {
    asm volatile("ldmatrix.sync.aligned.m8n8.x4.shared.b16 {%0,%1,%2,%3}, [%4];"
                 : "=r"(r[0]), "=r"(r[1]), "=r"(r[2]), "=r"(r[3]) : "r"(a));
}
__device__ __forceinline__ void ldsm4t(uint32_t* r, uint32_t a) {
    asm volatile("ldmatrix.sync.aligned.m8n8.x4.trans.shared.b16 {%0,%1,%2,%3}, [%4];"
                 : "=r"(r[0]), "=r"(r[1]), "=r"(r[2]), "=r"(r[3]) : "r"(a));
}
__device__ __forceinline__ void ldsm2(uint32_t* r, uint32_t a) {
    asm volatile("ldmatrix.sync.aligned.m8n8.x2.shared.b16 {%0,%1}, [%2];"
                 : "=r"(r[0]), "=r"(r[1]) : "r"(a));
}
__device__ __forceinline__ void mma16816(float* d, const uint32_t* a,
                                         uint32_t b0, uint32_t b1) {
    asm volatile(
        "mma.sync.aligned.m16n8k16.row.col.f32.f16.f16.f32 "
        "{%0,%1,%2,%3}, {%4,%5,%6,%7}, {%8,%9}, {%0,%1,%2,%3};"
        : "+f"(d[0]), "+f"(d[1]), "+f"(d[2]), "+f"(d[3])
        : "r"(a[0]), "r"(a[1]), "r"(a[2]), "r"(a[3]), "r"(b0), "r"(b1));
}
__device__ __forceinline__ uint32_t packh2(float a, float b) {
    __half2 h = __floats2half2_rn(a, b);
    return *(uint32_t*)&h;
}
__device__ __forceinline__ float2 h2f2(uint32_t u) {
    __half2 h = *(__half2*)&u;
    return __half22float2(h);
}

// ---------------------------------------------------------------------------
// fp32 -> fp16 hi/lo split (for x)
// ---------------------------------------------------------------------------
__global__ __launch_bounds__(256) void split_kernel(
    const float* __restrict__ src,
    __half* __restrict__ hi, __half* __restrict__ lo)
{
    int i = (blockIdx.x * 256 + threadIdx.x) * 4;
    float4 v = *(const float4*)(src + i);
    __half h0 = __float2half_rn(v.x), h1 = __float2half_rn(v.y);
    __half h2 = __float2half_rn(v.z), h3 = __float2half_rn(v.w);
    __half2 a; a.x = h0; a.y = h1;
    __half2 b; b.x = h2; b.y = h3;
    *(__half2*)(hi + i)     = a;
    *(__half2*)(hi + i + 2) = b;
    __half2 c, d;
    c.x = __float2half_rn(v.x - __half2float(h0));
    c.y = __float2half_rn(v.y - __half2float(h1));
    d.x = __float2half_rn(v.z - __half2float(h2));
    d.y = __float2half_rn(v.w - __half2float(h3));
    *(__half2*)(lo + i)     = c;
    *(__half2*)(lo + i + 2) = d;
}

// ---------------------------------------------------------------------------
// weight transpose: W [K][N] row-major -> WT [N][K] fp16 (hi only)
// ---------------------------------------------------------------------------
__global__ __launch_bounds__(256) void transpose_h_kernel(
    const float* __restrict__ Wq, const float* __restrict__ Wk,
    const float* __restrict__ Wv, const float* __restrict__ Wo,
    __half* __restrict__ out)
{
    __shared__ float tile[32][33];
    const int z = blockIdx.z;
    const float* W = (z == 0) ? Wq : (z == 1) ? Wk : (z == 2) ? Wv : Wo;
    __half* hi = out + (size_t)z * DD;
    const int n0 = blockIdx.x * 32, k0 = blockIdx.y * 32;
    const int tx = threadIdx.x & 31, ty = threadIdx.x >> 5;

    #pragma unroll
    for (int j = 0; j < 4; j++)
        tile[ty + 8 * j][tx] = W[(size_t)(k0 + ty + 8 * j) * 1024 + n0 + tx];
    __syncthreads();
    #pragma unroll
    for (int j = 0; j < 4; j++) {
        int n = ty + 8 * j;
        hi[(size_t)(n0 + n) * 1024 + k0 + tx] = __float2half_rn(tile[tx][n]);
    }
}

// ---------------------------------------------------------------------------
// mma.sync GEMM (2-pass): C = Ah@Bh + Al@Bh + bias
//   z=0: -> (Qh,Ql) scaled by SCALE2;  z=1: -> Kh only;  z=2: -> (Vh,Vl)
//   z=3: -> fp32 out
// 3-stage cp.async pipeline; 3 tiles per stage (Ah, Al, Bh).
// ---------------------------------------------------------------------------
#define TILE_B   10240            // 128 * 80
#define STAGE_B  (3 * TILE_B)     // 30720
#define GSMEM    (3 * STAGE_B)    // 92160

__global__ __launch_bounds__(256) void mma_gemm(
    const __half* __restrict__ Ain_h,
    const __half* __restrict__ Ain_l,
    const __half* __restrict__ WT,
    const float* bq, const float* bk, const float* bv, const float* bo,
    __half* Qh, __half* Ql, __half* Kh, __half* Vh, __half* Vl,
    float* outF, int zoff)
{
    extern __shared__ unsigned char dynsm[];
    const uint32_t sbase = smem_u32(dynsm);
    const int t    = threadIdx.x;
    const int wid  = t >> 5;
    const int lane = t & 31;

    const int z = blockIdx.z + zoff;
    const float* bias = (z == 0) ? bq : (z == 1) ? bk : (z == 2) ? bv : bo;
    const __half* Bh = WT + (size_t)z * DD;

    const int row0 = blockIdx.y * 128;
    const int col0 = blockIdx.x * 128;
    const int warp_m = wid >> 2;
    const int warp_n = wid & 3;

    const __half* gsrc[3] = { Ain_h, Ain_l, Bh };
    const int grow0[3] = { row0, row0, col0 };

    auto load_stage = [&](int stg, int c) {
        const uint32_t sb = sbase + stg * STAGE_B;
        #pragma unroll
        for (int i = 0; i < 6; i++) {
            int id   = t + i * 256;
            int tile = id >> 9;
            int rem  = id & 511;
            int r    = rem >> 2;
            int seg  = rem & 3;
            const __half* src =
                gsrc[tile] + (size_t)(grow0[tile] + r) * 1024 + c * 32 + seg * 8;
            cp_async16(sb + tile * TILE_B + r * 80 + seg * 16, src);
        }
        cp_commit();
    };

    float acc[4][4][4];
    #pragma unroll
    for (int i = 0; i < 4; i++)
        #pragma unroll
        for (int j = 0; j < 4; j++)
            #pragma unroll
            for (int e = 0; e < 4; e++) acc[i][j][e] = 0.f;

    load_stage(0, 0);
    load_stage(1, 1);

    for (int c = 0; c < 32; c++) {
        if (c + 2 < 32) { load_stage((c + 2) % 3, c + 2); cp_wait<2>(); }
        else if (c + 1 < 32) { cp_wait<1>(); }
        else { cp_wait<0>(); }
        __syncthreads();

        const uint32_t sb  = sbase + (c % 3) * STAGE_B;
        const uint32_t aAh = sb;
        const uint32_t aAl = sb + TILE_B;
        const uint32_t aBh = sb + 2 * TILE_B;

        #pragma unroll
        for (int ks = 0; ks < 2; ks++) {
            const uint32_t akb  = ((lane >> 4) * 8 + ks * 16) * 2;
            const uint32_t arow = warp_m * 64 + (lane & 15);
            const uint32_t bkb  = ((((lane >> 3) & 1) * 8) + ks * 16) * 2;
            const uint32_t brow = warp_n * 32 + (lane & 7);

            uint32_t ah[4][4], al[4][4], bh[4][2];
            #pragma unroll
            for (int i = 0; i < 4; i++)
                ldsm4(ah[i], aAh + (arow + i * 16) * 80 + akb);
            #pragma unroll
            for (int j = 0; j < 4; j++)
                ldsm2(bh[j], aBh + (brow + j * 8) * 80 + bkb);
            #pragma unroll
            for (int i = 0; i < 4; i++)
                #pragma unroll
                for (int j = 0; j < 4; j++)
                    mma16816(acc[i][j], ah[i], bh[j][0], bh[j][1]);
            #pragma unroll
            for (int i = 0; i < 4; i++)
                ldsm4(al[i], aAl + (arow + i * 16) * 80 + akb);
            #pragma unroll
            for (int i = 0; i < 4; i++)
                #pragma unroll
                for (int j = 0; j < 4; j++)
                    mma16816(acc[i][j], al[i], bh[j][0], bh[j][1]);
        }
        __syncthreads();
    }

    // ---- epilogue ----
    const int gid = lane >> 2, tig = lane & 3;
    __half* OH = (z == 0) ? Qh : (z == 1) ? Kh : Vh;
    __half* OL = (z == 0) ? Ql : Vl;
    const float sc = (z == 0) ? SCALE2 : 1.0f;

    #pragma unroll
    for (int i = 0; i < 4; i++) {
        #pragma unroll
        for (int j = 0; j < 4; j++) {
            int r  = row0 + warp_m * 64 + i * 16 + gid;
            int cc = col0 + warp_n * 32 + j * 8 + tig * 2;
            float b0 = bias[cc], b1 = bias[cc + 1];
            float v00 = acc[i][j][0] + b0, v01 = acc[i][j][1] + b1;
            float v10 = acc[i][j][2] + b0, v11 = acc[i][j][3] + b1;
            if (z == 3) {
                float2 a = { v00, v01 }, b = { v10, v11 };
                *(float2*)(outF + (size_t)r * 1024 + cc)       = a;
                *(float2*)(outF + (size_t)(r + 8) * 1024 + cc) = b;
            } else {
                v00 *= sc; v01 *= sc; v10 *= sc; v11 *= sc;
                uint32_t h0 = packh2(v00, v01);
                uint32_t h1 = packh2(v10, v11);
                *(uint32_t*)(OH + (size_t)r * 1024 + cc)       = h0;
                *(uint32_t*)(OH + (size_t)(r + 8) * 1024 + cc) = h1;
                if (z != 1) {   // K residual never consumed
                    float2 f0 = h2f2(h0), f1 = h2f2(h1);
                    uint32_t l0 = packh2(v00 - f0.x, v01 - f0.y);
                    uint32_t l1 = packh2(v10 - f1.x, v11 - f1.y);
                    *(uint32_t*)(OL + (size_t)r * 1024 + cc)       = l0;
                    *(uint32_t*)(OL + (size_t)(r + 8) * 1024 + cc) = l1;
                }
            }
        }
    }
}

// ---------------------------------------------------------------------------
// Tensor-core flash attention (causal).
// QK^T: 2-pass (Qh*Kh + Ql*Kh).  PV: 3-pass (Ph*Vh + Pl*Vh + Ph*Vl).
// CTA: (q-tile of 128, head, batch). 4 warps; warp = 32 q-rows x full width.
// ---------------------------------------------------------------------------
#define AT_PADB 144                    // smem row stride bytes (72 halves)
#define AQ_BYTES (128 * AT_PADB)       // 18432 per Q matrix
#define AKV_BYTES (64 * AT_PADB)       // 9216 per K/V matrix
#define AT_STAGE (3 * AKV_BYTES)       // Kh,Vh,Vl = 27648
#define AT_SMEM (2 * AQ_BYTES + 2 * AT_STAGE)   // 92160

__global__ __launch_bounds__(128) void attn_mma_kernel(
    const __half* __restrict__ Qh, const __half* __restrict__ Ql,
    const __half* __restrict__ Kh,
    const __half* __restrict__ Vh, const __half* __restrict__ Vl,
    __half* __restrict__ Ah, __half* __restrict__ Al)
{
    extern __shared__ unsigned char dynsm[];
    const uint32_t sbase = smem_u32(dynsm);
    const uint32_t sQh = sbase;
    const uint32_t sQl = sbase + AQ_BYTES;
    const uint32_t sKV = sbase + 2 * AQ_BYTES;

    const int t    = threadIdx.x;
    const int wid  = t >> 5;
    const int lane = t & 31;
    const int qi   = (int)gridDim.x - 1 - (int)blockIdx.x;  // big tiles first
    const int hd   = blockIdx.y;
    const int bb   = blockIdx.z;
    const int q0   = qi * 128;
    const int nkt  = 2 * qi + 2;
    const int m0   = wid * 32;

    const size_t base = (size_t)bb * S_ * D_ + (size_t)hd * DH;

    // ---- prologue: Q hi/lo ----
    {
        #pragma unroll
        for (int i = 0; i < 16; i++) {
            int id  = t + i * 128;
            int mat = id >> 10;
            int rem = id & 1023;
            int r   = rem >> 3;
            int seg = rem & 7;
            const __half* src = (mat == 0 ? Qh : Ql) + base + (size_t)(q0 + r) * D_ + seg * 8;
            cp_async16((mat == 0 ? sQh : sQl) + r * AT_PADB + seg * 16, src);
        }
    }
    auto load_kv = [&](int stg, int k0) {
        const uint32_t sb = sKV + stg * AT_STAGE;
        const __half* srcs[3] = { Kh, Vh, Vl };
        #pragma unroll
        for (int i = 0; i < 12; i++) {
            int id  = t + i * 128;
            int mat = id >> 9;
            int rem = id & 511;
            int r   = rem >> 3;
            int seg = rem & 7;
            const __half* src = srcs[mat] + base + (size_t)(k0 + r) * D_ + seg * 8;
            cp_async16(sb + mat * AKV_BYTES + r * AT_PADB + seg * 16, src);
        }
        cp_commit();
    };
    load_kv(0, 0);   // commits group containing Q + stage0

    float s[2][8][4];
    float o[2][8][4];
    float mrun[2][2], lrun[2][2];
    #pragma unroll
    for (int ma = 0; ma < 2; ma++) {
        #pragma unroll
        for (int n = 0; n < 8; n++)
            #pragma unroll
            for (int e = 0; e < 4; e++) o[ma][n][e] = 0.f;
        mrun[ma][0] = mrun[ma][1] = -1e30f;
        lrun[ma][0] = lrun[ma][1] = 0.f;
    }

    for (int kt = 0; kt < nkt; kt++) {
        const int k0 = kt * 64;
        if (kt + 1 < nkt) { load_kv((kt + 1) & 1, (kt + 1) * 64); cp_wait<1>(); }
        else              { cp_wait<0>(); }
        __syncthreads();

        const uint32_t stg = sKV + (kt & 1) * AT_STAGE;
        const uint32_t tKh = stg;
        const uint32_t tVh = stg + AKV_BYTES;
        const uint32_t tVl = stg + 2 * AKV_BYTES;

        // ---- S = Q K^T (2-pass) ----
        #pragma unroll
        for (int ma = 0; ma < 2; ma++)
            #pragma unroll
            for (int n = 0; n < 8; n++)
                #pragma unroll
                for (int e = 0; e < 4; e++) s[ma][n][e] = 0.f;

        #pragma unroll
        for (int ks = 0; ks < 4; ks++) {
            const uint32_t colb = ks * 32 + (lane >> 4) * 16;
            uint32_t ah[2][4], al[2][4];
            #pragma unroll
            for (int ma = 0; ma < 2; ma++) {
                uint32_t roff = (m0 + ma * 16 + (lane & 15)) * AT_PADB + colb;
                ldsm4(ah[ma], sQh + roff);
                ldsm4(al[ma], sQl + roff);
            }
            uint32_t kh[4][4];
            #pragma unroll
            for (int g = 0; g < 4; g++) {
                uint32_t roff = (g * 16 + (lane & 15)) * AT_PADB + colb;
                ldsm4(kh[g], tKh + roff);
            }
            #pragma unroll
            for (int ma = 0; ma < 2; ma++)
                #pragma unroll
                for (int n = 0; n < 8; n++) {
                    int g = n >> 1, odd = n & 1;
                    mma16816(s[ma][n], ah[ma], kh[g][odd], kh[g][odd + 2]);
                }
            #pragma unroll
            for (int ma = 0; ma < 2; ma++)
                #pragma unroll
                for (int n = 0; n < 8; n++) {
                    int g = n >> 1, odd = n & 1;
                    mma16816(s[ma][n], al[ma], kh[g][odd], kh[g][odd + 2]);
                }
        }

        // ---- causal mask (only tiles touching the diagonal) ----
        if (k0 + 63 > q0 + m0) {
            #pragma unroll
            for (int ma = 0; ma < 2; ma++)
                #pragma unroll
                for (int n = 0; n < 8; n++)
                    #pragma unroll
                    for (int e = 0; e < 4; e++) {
                        int row = q0 + m0 + ma * 16 + (lane >> 2) + (e >> 1) * 8;
                        int col = k0 + n * 8 + (lane & 3) * 2 + (e & 1);
                        if (col > row) s[ma][n][e] = -1e30f;
                    }
        }

        // ---- online softmax (log2 domain) ----
        #pragma unroll
        for (int ma = 0; ma < 2; ma++) {
            #pragma unroll
            for (int hh = 0; hh < 2; hh++) {
                float mx = -1e30f;
                #pragma unroll
                for (int n = 0; n < 8; n++)
                    mx = fmaxf(mx, fmaxf(s[ma][n][2 * hh], s[ma][n][2 * hh + 1]));
                mx = fmaxf(mx, __shfl_xor_sync(0xffffffffu, mx, 1));
                mx = fmaxf(mx, __shfl_xor_sync(0xffffffffu, mx, 2));
                float mnew = fmaxf(mrun[ma][hh], mx);
                float corr = exp2f(mrun[ma][hh] - mnew);
                mrun[ma][hh] = mnew;
                float ls = 0.f;
                #pragma unroll
                for (int n = 0; n < 8; n++) {
                    float p0 = exp2f(s[ma][n][2 * hh]     - mnew);
                    float p1 = exp2f(s[ma][n][2 * hh + 1] - mnew);
                    s[ma][n][2 * hh]     = p0;
                    s[ma][n][2 * hh + 1] = p1;
                    ls += p0 + p1;
                    o[ma][n][2 * hh]     *= corr;
                    o[ma][n][2 * hh + 1] *= corr;
                }
                ls += __shfl_xor_sync(0xffffffffu, ls, 1);
                ls += __shfl_xor_sync(0xffffffffu, ls, 2);
                lrun[ma][hh] = lrun[ma][hh] * corr + ls;
            }
        }

        // ---- O += P V (3-pass) ----
        #pragma unroll
        for (int ks = 0; ks < 4; ks++) {
            uint32_t aph[2][4], apl[2][4];
            #pragma unroll
            for (int ma = 0; ma < 2; ma++) {
                float p00 = s[ma][2*ks][0],   p01 = s[ma][2*ks][1];
                float p02 = s[ma][2*ks][2],   p03 = s[ma][2*ks][3];
                float p10 = s[ma][2*ks+1][0], p11 = s[ma][2*ks+1][1];
                float p12 = s[ma][2*ks+1][2], p13 = s[ma][2*ks+1][3];
                aph[ma][0] = packh2(p00, p01);
                aph[ma][1] = packh2(p02, p03);
                aph[ma][2] = packh2(p10, p11);
                aph[ma][3] = packh2(p12, p13);
                float2 f0 = h2f2(aph[ma][0]), f1 = h2f2(aph[ma][1]);
                float2 f2 = h2f2(aph[ma][2]), f3 = h2f2(aph[ma][3]);
                apl[ma][0] = packh2(p00 - f0.x, p01 - f0.y);
                apl[ma][1] = packh2(p02 - f1.x, p03 - f1.y);
                apl[ma][2] = packh2(p10 - f2.x, p11 - f2.y);
                apl[ma][3] = packh2(p12 - f3.x, p13 - f3.y);
            }
            uint32_t vh[4][4], vl[4][4];
            const int g = lane >> 3, li = lane & 7;
            #pragma unroll
            for (int nb = 0; nb < 4; nb++) {
                uint32_t roff = (uint32_t)(ks * 16 + (g & 1) * 8 + li) * AT_PADB
                              + (nb * 16 + (g >> 1) * 8) * 2;
                ldsm4t(vh[nb], tVh + roff);
                ldsm4t(vl[nb], tVl + roff);
            }
            #pragma unroll
            for (int ma = 0; ma < 2; ma++)
                #pragma unroll
                for (int n = 0; n < 8; n++) {
                    int nb = n >> 1, odd = (n & 1) * 2;
                    mma16816(o[ma][n], aph[ma], vh[nb][odd], vh[nb][odd + 1]);
                }
            #pragma unroll
            for (int ma = 0; ma < 2; ma++)
                #pragma unroll
                for (int n = 0; n < 8; n++) {
                    int nb = n >> 1, odd = (n & 1) * 2;
                    mma16816(o[ma][n], apl[ma], vh[nb][odd], vh[nb][odd + 1]);
                }
            #pragma unroll
            for (int ma = 0; ma < 2; ma++)
                #pragma unroll
                for (int n = 0; n < 8; n++) {
                    int nb = n >> 1, odd = (n & 1) * 2;
                    mma16816(o[ma][n], aph[ma], vl[nb][odd], vl[nb][odd + 1]);
                }
        }
        __syncthreads();
    }

    // ---- epilogue: normalize, split to half hi/lo for the Wo GEMM ----
    #pragma unroll
    for (int ma = 0; ma < 2; ma++) {
        float inv0 = 1.f / lrun[ma][0];
        float inv1 = 1.f / lrun[ma][1];
        int r0 = q0 + m0 + ma * 16 + (lane >> 2);
        #pragma unroll
        for (int n = 0; n < 8; n++) {
            int cc = hd * 64 + n * 8 + (lane & 3) * 2;
            float v00 = o[ma][n][0] * inv0, v01 = o[ma][n][1] * inv0;
            float v10 = o[ma][n][2] * inv1, v11 = o[ma][n][3] * inv1;
            uint32_t h0 = packh2(v00, v01);
            uint32_t h1 = packh2(v10, v11);
            float2 f0 = h2f2(h0), f1 = h2f2(h1);
            uint32_t l0 = packh2(v00 - f0.x, v01 - f0.y);
            uint32_t l1 = packh2(v10 - f1.x, v11 - f1.y);
            size_t a0 = (size_t)(bb * S_ + r0) * D_ + cc;
            size_t a1 = (size_t)(bb * S_ + r0 + 8) * D_ + cc;
            *(uint32_t*)(Ah + a0) = h0;
            *(uint32_t*)(Ah + a1) = h1;
            *(uint32_t*)(Al + a0) = l0;
            *(uint32_t*)(Al + a1) = l1;
        }
    }
}

// ---------------------------------------------------------------------------
extern "C" void kernel_launch(void* const* d_in, const int* in_sizes, int n_in,
                              void* d_out, int out_size)
{
    const float* x  = (const float*)d_in[0];
    const float* Wq = (const float*)d_in[1];
    const float* bq = (const float*)d_in[2];
    const float* Wk = (const float*)d_in[3];
    const float* bk = (const float*)d_in[4];
    const float* Wv = (const float*)d_in[5];
    const float* bv = (const float*)d_in[6];
    const float* Wo = (const float*)d_in[7];
    const float* bo = (const float*)d_in[8];
    float* out = (float*)d_out;

    __half *xh, *xl, *Qh, *Ql, *Kh, *Vh, *Vl, *Ahp, *Alp, *WTp;
    cudaGetSymbolAddress((void**)&xh,  g_xh);
    cudaGetSymbolAddress((void**)&xl,  g_xl);
    cudaGetSymbolAddress((void**)&Qh,  g_Qh);
    cudaGetSymbolAddress((void**)&Ql,  g_Ql);
    cudaGetSymbolAddress((void**)&Kh,  g_Kh);
    cudaGetSymbolAddress((void**)&Vh,  g_Vh);
    cudaGetSymbolAddress((void**)&Vl,  g_Vl);
    cudaGetSymbolAddress((void**)&Ahp, g_Ah);
    cudaGetSymbolAddress((void**)&Alp, g_Al);
    cudaGetSymbolAddress((void**)&WTp, g_WT);

    cudaFuncSetAttribute(mma_gemm,
                         cudaFuncAttributeMaxDynamicSharedMemorySize, GSMEM);
    cudaFuncSetAttribute(attn_mma_kernel,
                         cudaFuncAttributeMaxDynamicSharedMemorySize, AT_SMEM);

    // 1. split x into fp16 hi/lo
    split_kernel<<<M_ * D_ / 1024, 256>>>(x, xh, xl);
    // 2. transpose all four weights (hi only)
    transpose_h_kernel<<<dim3(32, 32, 4), 256>>>(Wq, Wk, Wv, Wo, WTp);
    // 3. fused Q/K/V projections -> split fp16 outputs (Q pre-scaled)
    mma_gemm<<<dim3(8, 32, 3), 256, GSMEM>>>(
        xh, xl, WTp, bq, bk, bv, bo, Qh, Ql, Kh, Vh, Vl, out, 0);
    // 4. tensor-core causal attention -> split fp16 output
    attn_mma_kernel<<<dim3(S_ / 128, H_, B_), 128, AT_SMEM>>>(
        Qh, Ql, Kh, Vh, Vl, Ahp, Alp);
    // 5. output projection -> d_out (fp32)
    mma_gemm<<<dim3(8, 32, 1), 256, GSMEM>>>(
        Ahp, Alp, WTp, bq, bk, bv, bo, Qh, Ql, Kh, Vh, Vl, out, 3);
}

// round 7
// speedup vs baseline: 5.3422x; 1.1324x over previous
#include <cuda_runtime.h>
#include <cuda_fp16.h>
#include <stdint.h>
#include <math.h>

#define B_  2
#define S_  2048
#define D_  1024
#define H_  16
#define DH  64
#define M_  (B_*S_)
#define DD  (D_*D_)
#define SCALE2 0.045084439f   // 1024^-0.5 * log2(e)

// ---------------- scratch (__device__ globals: allocation-free rule) -------
__device__ __half g_xh[M_*D_];
__device__ __half g_xl[M_*D_];
__device__ __half g_Qh[M_*D_];
__device__ __half g_Ql[M_*D_];
__device__ __half g_Kh[M_*D_];
__device__ __half g_Vh[M_*D_];
__device__ __half g_Ah[M_*D_];
__device__ __half g_Al[M_*D_];
// transposed weights (hi only): [q,k,v,o] x [N][K]
__device__ __half g_WT[4*DD];

// ---------------- generic-PTX helpers (compute_103-safe) -------------------
__device__ __forceinline__ uint32_t smem_u32(const void* p) {
    uint32_t a;
    asm("{ .reg .u64 t; cvta.to.shared.u64 t, %1; cvt.u32.u64 %0, t; }"
        : "=r"(a) : "l"(p));
    return a;
}
__device__ __forceinline__ void cp_async16(uint32_t dst, const void* src) {
    asm volatile("cp.async.cg.shared.global [%0], [%1], 16;"
                 :: "r"(dst), "l"(src) : "memory");
}
__device__ __forceinline__ void cp_commit() {
    asm volatile("cp.async.commit_group;" ::: "memory");
}
template <int N>
__device__ __forceinline__ void cp_wait() {
    asm volatile("cp.async.wait_group %0;" :: "n"(N) : "memory");
}
__device__ __forceinline__ void ldsm4(uint32_t* r, uint32_t a) {
    asm volatile("ldmatrix.sync.aligned.m8n8.x4.shared.b16 {%0,%1,%2,%3}, [%4];"
                 : "=r"(r[0]), "=r"(r[1]), "=r"(r[2]), "=r"(r[3]) : "r"(a));
}
__device__ __forceinline__ void ldsm4t(uint32_t* r, uint32_t a) {
    asm volatile("ldmatrix.sync.aligned.m8n8.x4.trans.shared.b16 {%0,%1,%2,%3}, [%4];"
                 : "=r"(r[0]), "=r"(r[1]), "=r"(r[2]), "=r"(r[3]) : "r"(a));
}
__device__ __forceinline__ void ldsm2(uint32_t* r, uint32_t a) {
    asm volatile("ldmatrix.sync.aligned.m8n8.x2.shared.b16 {%0,%1}, [%2];"
                 : "=r"(r[0]), "=r"(r[1]) : "r"(a));
}
__device__ __forceinline__ void mma16816(float* d, const uint32_t* a,
                                         uint32_t b0, uint32_t b1) {
    asm volatile(
        "mma.sync.aligned.m16n8k16.row.col.f32.f16.f16.f32 "
        "{%0,%1,%2,%3}, {%4,%5,%6,%7}, {%8,%9}, {%0,%1,%2,%3};"
        : "+f"(d[0]), "+f"(d[1]), "+f"(d[2]), "+f"(d[3])
        : "r"(a[0]), "r"(a[1]), "r"(a[2]), "r"(a[3]), "r"(b0), "r"(b1));
}
__device__ __forceinline__ uint32_t packh2(float a, float b) {
    __half2 h = __floats2half2_rn(a, b);
    return *(uint32_t*)&h;
}
__device__ __forceinline__ float2 h2f2(uint32_t u) {
    __half2 h = *(__half2*)&u;
    return __half22float2(h);
}

// ---------------------------------------------------------------------------
// fp32 -> fp16 hi/lo split (for x)
// ---------------------------------------------------------------------------
__global__ __launch_bounds__(256) void split_kernel(
    const float* __restrict__ src,
    __half* __restrict__ hi, __half* __restrict__ lo)
{
    int i = (blockIdx.x * 256 + threadIdx.x) * 4;
    float4 v = *(const float4*)(src + i);
    __half h0 = __float2half_rn(v.x), h1 = __float2half_rn(v.y);
    __half h2 = __float2half_rn(v.z), h3 = __float2half_rn(v.w);
    __half2 a; a.x = h0; a.y = h1;
    __half2 b; b.x = h2; b.y = h3;
    *(__half2*)(hi + i)     = a;
    *(__half2*)(hi + i + 2) = b;
    __half2 c, d;
    c.x = __float2half_rn(v.x - __half2float(h0));
    c.y = __float2half_rn(v.y - __half2float(h1));
    d.x = __float2half_rn(v.z - __half2float(h2));
    d.y = __float2half_rn(v.w - __half2float(h3));
    *(__half2*)(lo + i)     = c;
    *(__half2*)(lo + i + 2) = d;
}

// ---------------------------------------------------------------------------
// weight transpose: W [K][N] row-major -> WT [N][K] fp16 (hi only)
// ---------------------------------------------------------------------------
__global__ __launch_bounds__(256) void transpose_h_kernel(
    const float* __restrict__ Wq, const float* __restrict__ Wk,
    const float* __restrict__ Wv, const float* __restrict__ Wo,
    __half* __restrict__ out)
{
    __shared__ float tile[32][33];
    const int z = blockIdx.z;
    const float* W = (z == 0) ? Wq : (z == 1) ? Wk : (z == 2) ? Wv : Wo;
    __half* hi = out + (size_t)z * DD;
    const int n0 = blockIdx.x * 32, k0 = blockIdx.y * 32;
    const int tx = threadIdx.x & 31, ty = threadIdx.x >> 5;

    #pragma unroll
    for (int j = 0; j < 4; j++)
        tile[ty + 8 * j][tx] = W[(size_t)(k0 + ty + 8 * j) * 1024 + n0 + tx];
    __syncthreads();
    #pragma unroll
    for (int j = 0; j < 4; j++) {
        int n = ty + 8 * j;
        hi[(size_t)(n0 + n) * 1024 + k0 + tx] = __float2half_rn(tile[tx][n]);
    }
}

// ---------------------------------------------------------------------------
// mma.sync GEMM (2-pass): C = Ah@Bh + Al@Bh + bias
//   z=0: -> (Qh,Ql) scaled by SCALE2;  z=1: -> Kh;  z=2: -> Vh;  z=3: -> fp32
// 3-stage cp.async pipeline; 3 tiles per stage (Ah, Al, Bh).
// ---------------------------------------------------------------------------
#define TILE_B   10240            // 128 * 80
#define STAGE_B  (3 * TILE_B)     // 30720
#define GSMEM    (3 * STAGE_B)    // 92160

__global__ __launch_bounds__(256) void mma_gemm(
    const __half* __restrict__ Ain_h,
    const __half* __restrict__ Ain_l,
    const __half* __restrict__ WT,
    const float* bq, const float* bk, const float* bv, const float* bo,
    __half* Qh, __half* Ql, __half* Kh, __half* Vh,
    float* outF, int zoff)
{
    extern __shared__ unsigned char dynsm[];
    const uint32_t sbase = smem_u32(dynsm);
    const int t    = threadIdx.x;
    const int wid  = t >> 5;
    const int lane = t & 31;

    const int z = blockIdx.z + zoff;
    const float* bias = (z == 0) ? bq : (z == 1) ? bk : (z == 2) ? bv : bo;
    const __half* Bh = WT + (size_t)z * DD;

    const int row0 = blockIdx.y * 128;
    const int col0 = blockIdx.x * 128;
    const int warp_m = wid >> 2;
    const int warp_n = wid & 3;

    const __half* gsrc[3] = { Ain_h, Ain_l, Bh };
    const int grow0[3] = { row0, row0, col0 };

    auto load_stage = [&](int stg, int c) {
        const uint32_t sb = sbase + stg * STAGE_B;
        #pragma unroll
        for (int i = 0; i < 6; i++) {
            int id   = t + i * 256;
            int tile = id >> 9;
            int rem  = id & 511;
            int r    = rem >> 2;
            int seg  = rem & 3;
            const __half* src =
                gsrc[tile] + (size_t)(grow0[tile] + r) * 1024 + c * 32 + seg * 8;
            cp_async16(sb + tile * TILE_B + r * 80 + seg * 16, src);
        }
        cp_commit();
    };

    float acc[4][4][4];
    #pragma unroll
    for (int i = 0; i < 4; i++)
        #pragma unroll
        for (int j = 0; j < 4; j++)
            #pragma unroll
            for (int e = 0; e < 4; e++) acc[i][j][e] = 0.f;

    load_stage(0, 0);
    load_stage(1, 1);

    for (int c = 0; c < 32; c++) {
        if (c + 2 < 32) { load_stage((c + 2) % 3, c + 2); cp_wait<2>(); }
        else if (c + 1 < 32) { cp_wait<1>(); }
        else { cp_wait<0>(); }
        __syncthreads();

        const uint32_t sb  = sbase + (c % 3) * STAGE_B;
        const uint32_t aAh = sb;
        const uint32_t aAl = sb + TILE_B;
        const uint32_t aBh = sb + 2 * TILE_B;

        #pragma unroll
        for (int ks = 0; ks < 2; ks++) {
            const uint32_t akb  = ((lane >> 4) * 8 + ks * 16) * 2;
            const uint32_t arow = warp_m * 64 + (lane & 15);
            const uint32_t bkb  = ((((lane >> 3) & 1) * 8) + ks * 16) * 2;
            const uint32_t brow = warp_n * 32 + (lane & 7);

            uint32_t ah[4][4], al[4][4], bh[4][2];
            #pragma unroll
            for (int i = 0; i < 4; i++)
                ldsm4(ah[i], aAh + (arow + i * 16) * 80 + akb);
            #pragma unroll
            for (int j = 0; j < 4; j++)
                ldsm2(bh[j], aBh + (brow + j * 8) * 80 + bkb);
            #pragma unroll
            for (int i = 0; i < 4; i++)
                #pragma unroll
                for (int j = 0; j < 4; j++)
                    mma16816(acc[i][j], ah[i], bh[j][0], bh[j][1]);
            #pragma unroll
            for (int i = 0; i < 4; i++)
                ldsm4(al[i], aAl + (arow + i * 16) * 80 + akb);
            #pragma unroll
            for (int i = 0; i < 4; i++)
                #pragma unroll
                for (int j = 0; j < 4; j++)
                    mma16816(acc[i][j], al[i], bh[j][0], bh[j][1]);
        }
        __syncthreads();
    }

    // ---- epilogue ----
    const int gid = lane >> 2, tig = lane & 3;
    __half* OH = (z == 0) ? Qh : (z == 1) ? Kh : Vh;
    const float sc = (z == 0) ? SCALE2 : 1.0f;

    #pragma unroll
    for (int i = 0; i < 4; i++) {
        #pragma unroll
        for (int j = 0; j < 4; j++) {
            int r  = row0 + warp_m * 64 + i * 16 + gid;
            int cc = col0 + warp_n * 32 + j * 8 + tig * 2;
            float b0 = bias[cc], b1 = bias[cc + 1];
            float v00 = acc[i][j][0] + b0, v01 = acc[i][j][1] + b1;
            float v10 = acc[i][j][2] + b0, v11 = acc[i][j][3] + b1;
            if (z == 3) {
                float2 a = { v00, v01 }, b = { v10, v11 };
                *(float2*)(outF + (size_t)r * 1024 + cc)       = a;
                *(float2*)(outF + (size_t)(r + 8) * 1024 + cc) = b;
            } else {
                v00 *= sc; v01 *= sc; v10 *= sc; v11 *= sc;
                uint32_t h0 = packh2(v00, v01);
                uint32_t h1 = packh2(v10, v11);
                *(uint32_t*)(OH + (size_t)r * 1024 + cc)       = h0;
                *(uint32_t*)(OH + (size_t)(r + 8) * 1024 + cc) = h1;
                if (z == 0) {   // only Q needs a residual
                    float2 f0 = h2f2(h0), f1 = h2f2(h1);
                    uint32_t l0 = packh2(v00 - f0.x, v01 - f0.y);
                    uint32_t l1 = packh2(v10 - f1.x, v11 - f1.y);
                    *(uint32_t*)(Ql + (size_t)r * 1024 + cc)       = l0;
                    *(uint32_t*)(Ql + (size_t)(r + 8) * 1024 + cc) = l1;
                }
            }
        }
    }
}

// ---------------------------------------------------------------------------
// Tensor-core flash attention (causal).
// QK^T: 2-pass (Qh*Kh + Ql*Kh).  PV: 2-pass (Ph*Vh + Pl*Vh).
// CTA: (q-tile of 64, head, batch). 4 warps; warp = 16 q-rows x full width.
// smem 55 KB -> ~4 CTAs/SM.
// ---------------------------------------------------------------------------
#define AT_PADB 144                    // smem row stride bytes (72 halves)
#define AQ_BYTES (64 * AT_PADB)        // 9216 per Q matrix
#define AKV_BYTES (64 * AT_PADB)       // 9216 per K/V matrix
#define AT_STAGE (2 * AKV_BYTES)       // Kh,Vh = 18432
#define AT_SMEM (2 * AQ_BYTES + 2 * AT_STAGE)   // 55296

__global__ __launch_bounds__(128) void attn_mma_kernel(
    const __half* __restrict__ Qh, const __half* __restrict__ Ql,
    const __half* __restrict__ Kh, const __half* __restrict__ Vh,
    __half* __restrict__ Ah, __half* __restrict__ Al)
{
    extern __shared__ unsigned char dynsm[];
    const uint32_t sbase = smem_u32(dynsm);
    const uint32_t sQh = sbase;
    const uint32_t sQl = sbase + AQ_BYTES;
    const uint32_t sKV = sbase + 2 * AQ_BYTES;

    const int t    = threadIdx.x;
    const int wid  = t >> 5;
    const int lane = t & 31;
    const int qi   = (int)gridDim.x - 1 - (int)blockIdx.x;  // big tiles first
    const int hd   = blockIdx.y;
    const int bb   = blockIdx.z;
    const int q0   = qi * 64;
    const int nkt  = qi + 1;
    const int m0   = wid * 16;

    const size_t base = (size_t)bb * S_ * D_ + (size_t)hd * DH;

    // ---- prologue: Q hi/lo (64 rows x 128B each) ----
    {
        #pragma unroll
        for (int i = 0; i < 8; i++) {
            int id  = t + i * 128;        // 0..1023
            int mat = id >> 9;
            int rem = id & 511;
            int r   = rem >> 3;
            int seg = rem & 7;
            const __half* src = (mat == 0 ? Qh : Ql) + base + (size_t)(q0 + r) * D_ + seg * 8;
            cp_async16((mat == 0 ? sQh : sQl) + r * AT_PADB + seg * 16, src);
        }
    }
    auto load_kv = [&](int stg, int k0) {
        const uint32_t sb = sKV + stg * AT_STAGE;
        #pragma unroll
        for (int i = 0; i < 8; i++) {
            int id  = t + i * 128;        // 0..1023
            int mat = id >> 9;
            int rem = id & 511;
            int r   = rem >> 3;
            int seg = rem & 7;
            const __half* src = (mat == 0 ? Kh : Vh) + base + (size_t)(k0 + r) * D_ + seg * 8;
            cp_async16(sb + mat * AKV_BYTES + r * AT_PADB + seg * 16, src);
        }
        cp_commit();
    };
    load_kv(0, 0);   // commits group containing Q + stage0

    float s[8][4];
    float o[8][4];
    float mrun[2], lrun[2];
    #pragma unroll
    for (int n = 0; n < 8; n++)
        #pragma unroll
        for (int e = 0; e < 4; e++) o[n][e] = 0.f;
    mrun[0] = mrun[1] = -1e30f;
    lrun[0] = lrun[1] = 0.f;

    for (int kt = 0; kt < nkt; kt++) {
        const int k0 = kt * 64;
        if (kt + 1 < nkt) { load_kv((kt + 1) & 1, (kt + 1) * 64); cp_wait<1>(); }
        else              { cp_wait<0>(); }
        __syncthreads();

        const uint32_t stg = sKV + (kt & 1) * AT_STAGE;
        const uint32_t tKh = stg;
        const uint32_t tVh = stg + AKV_BYTES;

        // ---- S = Q K^T (2-pass) ----
        #pragma unroll
        for (int n = 0; n < 8; n++)
            #pragma unroll
            for (int e = 0; e < 4; e++) s[n][e] = 0.f;

        #pragma unroll
        for (int ks = 0; ks < 4; ks++) {
            const uint32_t colb = ks * 32 + (lane >> 4) * 16;
            uint32_t ah[4], al[4];
            {
                uint32_t roff = (m0 + (lane & 15)) * AT_PADB + colb;
                ldsm4(ah, sQh + roff);
                ldsm4(al, sQl + roff);
            }
            uint32_t kh[4][4];
            #pragma unroll
            for (int g = 0; g < 4; g++) {
                uint32_t roff = (g * 16 + (lane & 15)) * AT_PADB + colb;
                ldsm4(kh[g], tKh + roff);
            }
            #pragma unroll
            for (int n = 0; n < 8; n++) {
                int g = n >> 1, odd = n & 1;
                mma16816(s[n], ah, kh[g][odd], kh[g][odd + 2]);
            }
            #pragma unroll
            for (int n = 0; n < 8; n++) {
                int g = n >> 1, odd = n & 1;
                mma16816(s[n], al, kh[g][odd], kh[g][odd + 2]);
            }
        }

        // ---- causal mask (only tiles touching the diagonal) ----
        if (k0 + 63 > q0 + m0) {
            #pragma unroll
            for (int n = 0; n < 8; n++)
                #pragma unroll
                for (int e = 0; e < 4; e++) {
                    int row = q0 + m0 + (lane >> 2) + (e >> 1) * 8;
                    int col = k0 + n * 8 + (lane & 3) * 2 + (e & 1);
                    if (col > row) s[n][e] = -1e30f;
                }
        }

        // ---- online softmax (log2 domain) ----
        #pragma unroll
        for (int hh = 0; hh < 2; hh++) {
            float mx = -1e30f;
            #pragma unroll
            for (int n = 0; n < 8; n++)
                mx = fmaxf(mx, fmaxf(s[n][2 * hh], s[n][2 * hh + 1]));
            mx = fmaxf(mx, __shfl_xor_sync(0xffffffffu, mx, 1));
            mx = fmaxf(mx, __shfl_xor_sync(0xffffffffu, mx, 2));
            float mnew = fmaxf(mrun[hh], mx);
            float corr = exp2f(mrun[hh] - mnew);
            mrun[hh] = mnew;
            float ls = 0.f;
            #pragma unroll
            for (int n = 0; n < 8; n++) {
                float p0 = exp2f(s[n][2 * hh]     - mnew);
                float p1 = exp2f(s[n][2 * hh + 1] - mnew);
                s[n][2 * hh]     = p0;
                s[n][2 * hh + 1] = p1;
                ls += p0 + p1;
                o[n][2 * hh]     *= corr;
                o[n][2 * hh + 1] *= corr;
            }
            ls += __shfl_xor_sync(0xffffffffu, ls, 1);
            ls += __shfl_xor_sync(0xffffffffu, ls, 2);
            lrun[hh] = lrun[hh] * corr + ls;
        }

        // ---- O += P V (2-pass: Ph*Vh + Pl*Vh) ----
        #pragma unroll
        for (int ks = 0; ks < 4; ks++) {
            uint32_t aph[4], apl[4];
            {
                float p00 = s[2*ks][0],   p01 = s[2*ks][1];
                float p02 = s[2*ks][2],   p03 = s[2*ks][3];
                float p10 = s[2*ks+1][0], p11 = s[2*ks+1][1];
                float p12 = s[2*ks+1][2], p13 = s[2*ks+1][3];
                aph[0] = packh2(p00, p01);
                aph[1] = packh2(p02, p03);
                aph[2] = packh2(p10, p11);
                aph[3] = packh2(p12, p13);
                float2 f0 = h2f2(aph[0]), f1 = h2f2(aph[1]);
                float2 f2 = h2f2(aph[2]), f3 = h2f2(aph[3]);
                apl[0] = packh2(p00 - f0.x, p01 - f0.y);
                apl[1] = packh2(p02 - f1.x, p03 - f1.y);
                apl[2] = packh2(p10 - f2.x, p11 - f2.y);
                apl[3] = packh2(p12 - f3.x, p13 - f3.y);
            }
            uint32_t vh[4][4];
            const int g = lane >> 3, li = lane & 7;
            #pragma unroll
            for (int nb = 0; nb < 4; nb++) {
                uint32_t roff = (uint32_t)(ks * 16 + (g & 1) * 8 + li) * AT_PADB
                              + (nb * 16 + (g >> 1) * 8) * 2;
                ldsm4t(vh[nb], tVh + roff);
            }
            #pragma unroll
            for (int n = 0; n < 8; n++) {
                int nb = n >> 1, odd = (n & 1) * 2;
                mma16816(o[n], aph, vh[nb][odd], vh[nb][odd + 1]);
            }
            #pragma unroll
            for (int n = 0; n < 8; n++) {
                int nb = n >> 1, odd = (n & 1) * 2;
                mma16816(o[n], apl, vh[nb][odd], vh[nb][odd + 1]);
            }
        }
        __syncthreads();
    }

    // ---- epilogue: normalize, split to half hi/lo for the Wo GEMM ----
    {
        float inv0 = 1.f / lrun[0];
        float inv1 = 1.f / lrun[1];
        int r0 = q0 + m0 + (lane >> 2);
        #pragma unroll
        for (int n = 0; n < 8; n++) {
            int cc = hd * 64 + n * 8 + (lane & 3) * 2;
            float v00 = o[n][0] * inv0, v01 = o[n][1] * inv0;
            float v10 = o[n][2] * inv1, v11 = o[n][3] * inv1;
            uint32_t h0 = packh2(v00, v01);
            uint32_t h1 = packh2(v10, v11);
            float2 f0 = h2f2(h0), f1 = h2f2(h1);
            uint32_t l0 = packh2(v00 - f0.x, v01 - f0.y);
            uint32_t l1 = packh2(v10 - f1.x, v11 - f1.y);
            size_t a0 = (size_t)(bb * S_ + r0) * D_ + cc;
            size_t a1 = (size_t)(bb * S_ + r0 + 8) * D_ + cc;
            *(uint32_t*)(Ah + a0) = h0;
            *(uint32_t*)(Ah + a1) = h1;
            *(uint32_t*)(Al + a0) = l0;
            *(uint32_t*)(Al + a1) = l1;
        }
    }
}

// ---------------------------------------------------------------------------
extern "C" void kernel_launch(void* const* d_in, const int* in_sizes, int n_in,
                              void* d_out, int out_size)
{
    const float* x  = (const float*)d_in[0];
    const float* Wq = (const float*)d_in[1];
    const float* bq = (const float*)d_in[2];
    const float* Wk = (const float*)d_in[3];
    const float* bk = (const float*)d_in[4];
    const float* Wv = (const float*)d_in[5];
    const float* bv = (const float*)d_in[6];
    const float* Wo = (const float*)d_in[7];
    const float* bo = (const float*)d_in[8];
    float* out = (float*)d_out;

    __half *xh, *xl, *Qh, *Ql, *Kh, *Vh, *Ahp, *Alp, *WTp;
    cudaGetSymbolAddress((void**)&xh,  g_xh);
    cudaGetSymbolAddress((void**)&xl,  g_xl);
    cudaGetSymbolAddress((void**)&Qh,  g_Qh);
    cudaGetSymbolAddress((void**)&Ql,  g_Ql);
    cudaGetSymbolAddress((void**)&Kh,  g_Kh);
    cudaGetSymbolAddress((void**)&Vh,  g_Vh);
    cudaGetSymbolAddress((void**)&Ahp, g_Ah);
    cudaGetSymbolAddress((void**)&Alp, g_Al);
    cudaGetSymbolAddress((void**)&WTp, g_WT);

    cudaFuncSetAttribute(mma_gemm,
                         cudaFuncAttributeMaxDynamicSharedMemorySize, GSMEM);
    cudaFuncSetAttribute(attn_mma_kernel,
                         cudaFuncAttributeMaxDynamicSharedMemorySize, AT_SMEM);

    // 1. split x into fp16 hi/lo
    split_kernel<<<M_ * D_ / 1024, 256>>>(x, xh, xl);
    // 2. transpose all four weights (hi only)
    transpose_h_kernel<<<dim3(32, 32, 4), 256>>>(Wq, Wk, Wv, Wo, WTp);
    // 3. fused Q/K/V projections -> fp16 outputs (Q pre-scaled, Q keeps lo)
    mma_gemm<<<dim3(8, 32, 3), 256, GSMEM>>>(
        xh, xl, WTp, bq, bk, bv, bo, Qh, Ql, Kh, Vh, out, 0);
    // 4. tensor-core causal attention -> split fp16 output
    attn_mma_kernel<<<dim3(S_ / 64, H_, B_), 128, AT_SMEM>>>(
        Qh, Ql, Kh, Vh, Ahp, Alp);
    // 5. output projection -> d_out (fp32)
    mma_gemm<<<dim3(8, 32, 1), 256, GSMEM>>>(
        Ahp, Alp, WTp, bq, bk, bv, bo, Qh, Ql, Kh, Vh, out, 3);
}